// round 12
// baseline (speedup 1.0000x reference)
#include <cuda_runtime.h>
#include <cuda_fp16.h>
#include <cstdint>
#include <math.h>

#define BB 4
#define SS 2048
#define DD 1024
#define EE 1536
#define HH 4096
#define TT (BB*SS)   /* 8192 tokens */
#define NC 16        /* scan chunks */
#define CL (SS/NC)   /* 128 steps per chunk */
#define NLANE (BB*EE)

typedef __half fp16;

// ---------------- scratch (allocation-free: __device__ globals) ----------------
__device__ fp16  g_dwa[(size_t)TT*DD];
__device__ fp16  g_t1h[(size_t)TT*DD];         // residual stream pre-LN (fp16)
__device__ fp16  g_x1a[(size_t)TT*DD];
__device__ float g_gates[(size_t)2*TT*EE];     // [lgf | lv] planes
__device__ fp16  g_ha [(size_t)TT*EE];
__device__ fp16  g_x2a[(size_t)TT*DD];
__device__ fp16  g_ma [(size_t)TT*HH];
// chunked-scan state
__device__ float g_cA[NC*NLANE], g_cM[NC*NLANE], g_cR[NC*NLANE];
__device__ float g_pA[NC*NLANE], g_pM[NC*NLANE], g_pR[NC*NLANE];
// weights (fp16)
__device__ fp16 g_pwh[DD*DD];
__device__ fp16 g_wgh[3*EE*DD];   // rows [0,EE): w_f ; rows [EE,3EE): wi/wh 8-row interleave
__device__ fp16 g_wdh[DD*EE];
__device__ fp16 g_m1h[HH*DD];
__device__ fp16 g_m2h[DD*HH];

// ---------------- math helpers ----------------
__device__ __forceinline__ float logsig(float z) {
    return z >= 0.f ? -log1pf(expf(-z)) : z - log1pf(expf(z));
}
__device__ __forceinline__ float loggf(float x) {
    return x >= 0.f ? logf(x + 0.5f) : logsig(x);
}
__device__ __forceinline__ float gelu_exact(float x) {
    return 0.5f * x * (1.f + erff(x * 0.70710678118654752f));
}
template<int ACT>
__device__ __forceinline__ float apply_act(float v) {
    if (ACT == 1) return logsig(v);
    if (ACT == 3) return gelu_exact(v);
    return v;
}

__device__ __forceinline__ uint32_t smem_u32(const void* p) {
    uint32_t a;
    asm("{ .reg .u64 t; cvta.to.shared.u64 t, %1; cvt.u32.u64 %0, t; }" : "=r"(a) : "l"(p));
    return a;
}

#define LDMX4(d0,d1,d2,d3,addr) \
    asm volatile("ldmatrix.sync.aligned.m8n8.x4.shared.b16 {%0,%1,%2,%3}, [%4];" \
        : "=r"(d0), "=r"(d1), "=r"(d2), "=r"(d3) : "r"(addr))

__device__ __forceinline__ void mma16816(float* c, const uint32_t* a, const uint32_t* b) {
    asm volatile(
        "mma.sync.aligned.m16n8k16.row.col.f32.f16.f16.f32 "
        "{%0,%1,%2,%3}, {%4,%5,%6,%7}, {%8,%9}, {%0,%1,%2,%3};"
        : "+f"(c[0]), "+f"(c[1]), "+f"(c[2]), "+f"(c[3])
        : "r"(a[0]), "r"(a[1]), "r"(a[2]), "r"(a[3]), "r"(b[0]), "r"(b[1]));
}

// ---------------- HMMA GEMM ----------------
// 128x128 CTA tile, 128 threads (2x2 warps, 64x64 warp tile), BK=64, 2-stage,
// 2 CTA/SM. 32 MMA per 8 ldmatrix per sub-step (issue-density experiment).
static const int TILE_B  = 16384;
static const int STAGE_B = 2 * TILE_B;         // A, Bh
static const int GEMM_SMEM = 2 * STAGE_B + 1024;

// ACT==4: fused gate mode. bn<EE -> lgf plane (logsig). bn>=EE -> paired wi/wh
// fragments in the same thread; epilogue emits lv = logsig(zi)+loggf(zh).
template<int ACT, bool OUTF, bool OUTB>
__global__ __launch_bounds__(128, 2)
void hm_gemm(const fp16* __restrict__ A, const fp16* __restrict__ Bh,
             const float* __restrict__ bias, const float* __restrict__ res,
             float* __restrict__ Cf, fp16* __restrict__ Ch,
             int M, int N, int K)
{
    extern __shared__ char smem[];
    uint32_t sb = (smem_u32(smem) + 1023) & ~1023u;
    int tid = threadIdx.x;
    int lane = tid & 31, wid = tid >> 5;
    int wm = wid & 1, wn = wid >> 1;          // 2 x 2 warp grid, 64x64 per warp
    int bm = blockIdx.y * 128, bn = blockIdx.x * 128;
    const int NK = K >> 6;

    float acc[4][8][4];
    #pragma unroll
    for (int i = 0; i < 4; i++)
        #pragma unroll
        for (int j = 0; j < 8; j++)
            #pragma unroll
            for (int q = 0; q < 4; q++) acc[i][j][q] = 0.f;

    auto load_chunk = [&](int c) {
        uint32_t tb = sb + (c & 1) * STAGE_B;
        int k0 = c << 6;
        #pragma unroll
        for (int i = 0; i < 16; i++) {
            int idx = tid + (i << 7);         // 2048 float4 total
            int t = i >> 3;                   // 0: A, 1: B (const per i)
            int local = idx & 1023;
            int r = local >> 3;
            int ch = local & 7;
            const fp16* base = (t == 0) ? A : Bh;
            int rowoff = (t == 0) ? bm : bn;
            const fp16* src = base + (size_t)(rowoff + r) * K + k0 + ch * 8;
            uint32_t dst = tb + t * TILE_B + r * 128 + ((ch ^ (r & 7)) * 16);
            asm volatile("cp.async.cg.shared.global [%0], [%1], 16;" :: "r"(dst), "l"(src));
        }
        asm volatile("cp.async.commit_group;");
    };

    load_chunk(0);

    for (int c = 0; c < NK; c++) {
        if (c + 1 < NK) {
            load_chunk(c + 1);
            asm volatile("cp.async.wait_group 1;");
        } else {
            asm volatile("cp.async.wait_group 0;");
        }
        __syncthreads();

        uint32_t tb  = sb + (c & 1) * STAGE_B;
        uint32_t tA  = tb;
        uint32_t tBh = tb + TILE_B;

        int khalf = lane >> 4;
        int rlo = lane & 15;

        #pragma unroll
        for (int sub = 0; sub < 4; sub++) {
            int c16 = sub * 2 + khalf;
            uint32_t bh[8][2];
            #pragma unroll
            for (int p = 0; p < 4; p++) {
                int r = wn * 64 + p * 16 + rlo;
                uint32_t addr = r * 128 + ((c16 ^ (r & 7)) * 16);
                uint32_t t0, t1, t2, t3;
                LDMX4(t0, t1, t2, t3, tBh + addr);
                bh[2*p][0] = t0; bh[2*p][1] = t2; bh[2*p+1][0] = t1; bh[2*p+1][1] = t3;
            }
            #pragma unroll
            for (int i = 0; i < 4; i++) {
                int r = wm * 64 + i * 16 + rlo;
                uint32_t addr = r * 128 + ((c16 ^ (r & 7)) * 16);
                uint32_t ah[4];
                LDMX4(ah[0], ah[1], ah[2], ah[3], tA + addr);
                #pragma unroll
                for (int j = 0; j < 8; j++) {
                    mma16816(acc[i][j], ah, bh[j]);
                }
            }
        }
        __syncthreads();
    }

    // ---- epilogue ----
    if (ACT == 4) {
        if (bn < EE) {
            // forget gate -> plane0 (lgf)
            #pragma unroll
            for (int i = 0; i < 4; i++) {
                #pragma unroll
                for (int j = 0; j < 8; j++) {
                    int r0 = bm + wm * 64 + i * 16 + (lane >> 2);
                    int c0 = bn + wn * 64 + j * 8 + (lane & 3) * 2;
                    #pragma unroll
                    for (int half = 0; half < 2; half++) {
                        int row = r0 + half * 8;
                        float v0 = logsig(acc[i][j][half * 2 + 0]);
                        float v1 = logsig(acc[i][j][half * 2 + 1]);
                        float2 w2; w2.x = v0; w2.y = v1;
                        *(float2*)(Cf + (size_t)row * EE + c0) = w2;
                    }
                }
            }
        } else {
            // combined wi/wh tiles -> plane1 (lv = logsig(zi) + loggf(zh))
            int qt = (bn - EE) >> 7;
            float* lvp = Cf + (size_t)TT * EE;
            #pragma unroll
            for (int i = 0; i < 4; i++) {
                #pragma unroll
                for (int j = 0; j < 8; j += 2) {
                    int r0 = bm + wm * 64 + i * 16 + (lane >> 2);
                    int grp = (wn * 8 + j) >> 1;
                    int e0 = qt * 64 + grp * 8 + (lane & 3) * 2;
                    #pragma unroll
                    for (int half = 0; half < 2; half++) {
                        int row = r0 + half * 8;
                        float v0 = logsig(acc[i][j][half*2+0]) + loggf(acc[i][j+1][half*2+0]);
                        float v1 = logsig(acc[i][j][half*2+1]) + loggf(acc[i][j+1][half*2+1]);
                        float2 w2; w2.x = v0; w2.y = v1;
                        *(float2*)(lvp + (size_t)row * EE + e0) = w2;
                    }
                }
            }
        }
        return;
    }

    #pragma unroll
    for (int i = 0; i < 4; i++) {
        #pragma unroll
        for (int j = 0; j < 8; j++) {
            int r0 = bm + wm * 64 + i * 16 + (lane >> 2);
            int c0 = bn + wn * 64 + j * 8 + (lane & 3) * 2;
            #pragma unroll
            for (int half = 0; half < 2; half++) {
                int row = r0 + half * 8;
                float v0 = acc[i][j][half * 2 + 0];
                float v1 = acc[i][j][half * 2 + 1];
                if (bias) { v0 += __ldg(bias + c0); v1 += __ldg(bias + c0 + 1); }
                v0 = apply_act<ACT>(v0);
                v1 = apply_act<ACT>(v1);
                size_t o = (size_t)row * N + c0;
                if (res) {
                    float2 r2 = *(const float2*)(res + o);
                    v0 += r2.x; v1 += r2.y;
                }
                if (OUTF) {
                    float2 w2; w2.x = v0; w2.y = v1;
                    *(float2*)(Cf + o) = w2;
                }
                if (OUTB) {
                    __half2 h2;
                    h2.x = __float2half_rn(v0);
                    h2.y = __float2half_rn(v1);
                    *(__half2*)(Ch + o) = h2;
                }
            }
        }
    }
}

// ---------------- weight rounding (fp32 -> fp16) ----------------
__device__ __forceinline__ void round4(const float* __restrict__ src,
                                       fp16* __restrict__ hi, int li) {
    float4 x = ((const float4*)src)[li];
    __half2 h0, h1;
    h0.x = __float2half_rn(x.x); h0.y = __float2half_rn(x.y);
    h1.x = __float2half_rn(x.z); h1.y = __float2half_rn(x.w);
    ((__half2*)hi)[2*li]   = h0;
    ((__half2*)hi)[2*li+1] = h1;
}
__device__ __forceinline__ void round4_sd(const float* __restrict__ src, int si,
                                          fp16* __restrict__ dst, int di) {
    float4 x = ((const float4*)src)[si];
    __half2 h0, h1;
    h0.x = __float2half_rn(x.x); h0.y = __float2half_rn(x.y);
    h1.x = __float2half_rn(x.z); h1.y = __float2half_rn(x.w);
    ((__half2*)dst)[2*di]   = h0;
    ((__half2*)dst)[2*di+1] = h1;
}

// segment sizes in float4 units
#define S_PW (DD*DD/4)
#define S_WG (EE*DD/4)
#define S_WD (DD*EE/4)
#define S_M  (HH*DD/4)
#define C4   (DD/4)     /* float4 per row */

__global__ void splitA_kernel(const float* __restrict__ pw, const float* __restrict__ wf,
                              const float* __restrict__ wi, const float* __restrict__ wh) {
    int i = blockIdx.x * blockDim.x + threadIdx.x;
    if (i >= S_PW + 3*S_WG) return;
    if (i < S_PW) { round4(pw, g_pwh, i); return; }
    int k = i - S_PW;
    if (k < S_WG) { round4(wf, g_wgh, k); return; }   // rows [0,EE): w_f
    // interleaved wi/wh region: buffer rows [EE, 3EE)
    int k2 = k - S_WG;                // float4 index within interleave region
    int r  = k2 / C4;                 // interleave row 0..2EE-1
    int c4 = k2 % C4;
    int blk = r >> 4;
    int w   = r & 15;
    const float* src = (w < 8) ? wi : wh;
    int srow = blk * 8 + (w & 7);
    round4_sd(src, srow * C4 + c4, g_wgh, S_WG + k2);
}
__global__ void splitB_kernel(const float* __restrict__ wd, const float* __restrict__ m1,
                              const float* __restrict__ m2) {
    int i = blockIdx.x * blockDim.x + threadIdx.x;
    if (i >= S_WD + 2*S_M) return;
    if (i < S_WD)            round4(wd, g_wdh, i);
    else if (i < S_WD + S_M) round4(m1, g_m1h, i - S_WD);
    else                     round4(m2, g_m2h, i - S_WD - S_M);
}

// ---------------- depthwise causal conv (K=4), emits fp16 ----------------
__global__ void dwconv_kernel(const float* __restrict__ x,
                              const float* __restrict__ w,
                              const float* __restrict__ b,
                              fp16* __restrict__ oa) {
    int idx = blockIdx.x * blockDim.x + threadIdx.x;
    int d = idx & (DD - 1);
    int t = idx >> 10;
    int s = t & (SS - 1);
    float acc = b[d];
    float w0 = w[d*4+0], w1 = w[d*4+1], w2 = w[d*4+2], w3 = w[d*4+3];
    if (s >= 3) acc += w0 * x[(size_t)(t-3)*DD + d];
    if (s >= 2) acc += w1 * x[(size_t)(t-2)*DD + d];
    if (s >= 1) acc += w2 * x[(size_t)(t-1)*DD + d];
    acc += w3 * x[(size_t)t*DD + d];
    oa[idx] = __float2half_rn(acc);
}

// ---------------- LayerNorm (D=1024), fp16 in, fp16 out ----------------
__global__ void ln_kernel(const fp16* __restrict__ in, const float* __restrict__ g,
                          const float* __restrict__ beta, fp16* __restrict__ oa) {
    int t = blockIdx.x;
    int i = threadIdx.x;   // 0..255, each 4 halves
    uint2 raw = ((const uint2*)(in + (size_t)t*DD))[i];
    __half2 p0 = *(__half2*)&raw.x;
    __half2 p1 = *(__half2*)&raw.y;
    float v0 = __half2float(p0.x), v1 = __half2float(p0.y);
    float v2 = __half2float(p1.x), v3 = __half2float(p1.y);
    float s  = v0 + v1 + v2 + v3;
    float s2 = v0*v0 + v1*v1 + v2*v2 + v3*v3;
    #pragma unroll
    for (int o = 16; o; o >>= 1) {
        s  += __shfl_xor_sync(0xffffffffu, s,  o);
        s2 += __shfl_xor_sync(0xffffffffu, s2, o);
    }
    __shared__ float ss[8], ss2[8];
    int w = i >> 5, l = i & 31;
    if (!l) { ss[w] = s; ss2[w] = s2; }
    __syncthreads();
    if (w == 0) {
        s  = (l < 8) ? ss[l]  : 0.f;
        s2 = (l < 8) ? ss2[l] : 0.f;
        #pragma unroll
        for (int o = 4; o; o >>= 1) {
            s  += __shfl_xor_sync(0xffffffffu, s,  o);
            s2 += __shfl_xor_sync(0xffffffffu, s2, o);
        }
        if (!l) { ss[0] = s; ss2[0] = s2; }
    }
    __syncthreads();
    float mu  = ss[0] * (1.f / DD);
    float var = ss2[0] * (1.f / DD) - mu * mu;
    float inv = rsqrtf(var + 1e-5f);
    float4 gg = ((const float4*)g)[i];
    float4 bb = ((const float4*)beta)[i];
    __half2 h0, h1;
    h0.x = __float2half_rn((v0 - mu) * inv * gg.x + bb.x);
    h0.y = __float2half_rn((v1 - mu) * inv * gg.y + bb.y);
    h1.x = __float2half_rn((v2 - mu) * inv * gg.z + bb.z);
    h1.y = __float2half_rn((v3 - mu) * inv * gg.w + bb.w);
    size_t base = (size_t)t * DD;
    ((__half2*)(oa + base))[2*i]   = h0;
    ((__half2*)(oa + base))[2*i+1] = h1;
}

// ---------------- chunked minLSTM scan: 3 phases (2-plane gates) ----------------
__global__ void scanA_kernel(const float* __restrict__ gates) {
    int id = blockIdx.x * blockDim.x + threadIdx.x;
    if (id >= NC * NLANE) return;
    int c = id / NLANE;
    int rem = id % NLANE;
    int b = rem / EE, e = rem % EE;
    const float* lf = gates + ((size_t)b * SS + c * CL) * EE + e;
    const float* lv = lf + (size_t)TT * EE;
    float Aloc = 0.f, M = -1e30f, R = 0.f;
    for (int s = 0; s < CL; s++) {
        size_t off = (size_t)s * EE;
        Aloc += lf[off];
        float t = lv[off] - Aloc;
        if (t <= M) {
            R += expf(t - M);
        } else {
            R = R * expf(M - t) + 1.f;
            M = t;
        }
    }
    g_cA[id] = Aloc; g_cM[id] = M; g_cR[id] = R;
}

__global__ void scanB_kernel() {
    int lane = blockIdx.x * blockDim.x + threadIdx.x;
    if (lane >= NLANE) return;
    float Aprev = 0.f;
    float Mg = -0.6931471805599453f;   // log 0.5
    float Rg = 1.f;
    #pragma unroll
    for (int c = 0; c < NC; c++) {
        int idx = c * NLANE + lane;
        g_pA[idx] = Aprev; g_pM[idx] = Mg; g_pR[idx] = Rg;
        float Mc = g_cM[idx] - Aprev;
        float Rc = g_cR[idx];
        if (Mc <= Mg) {
            Rg += Rc * expf(Mc - Mg);
        } else {
            Rg = Rg * expf(Mg - Mc) + Rc;
            Mg = Mc;
        }
        Aprev += g_cA[idx];
    }
}

__global__ void scanC_kernel(const float* __restrict__ gates, fp16* __restrict__ ha) {
    int id = blockIdx.x * blockDim.x + threadIdx.x;
    if (id >= NC * NLANE) return;
    int c = id / NLANE;
    int rem = id % NLANE;
    int b = rem / EE, e = rem % EE;
    const float* lf = gates + ((size_t)b * SS + c * CL) * EE + e;
    const float* lv = lf + (size_t)TT * EE;
    fp16* ph = ha + ((size_t)b * SS + c * CL) * EE + e;
    float A0 = g_pA[id];
    float m  = g_pM[id];
    float r  = g_pR[id];
    float Aloc = 0.f;
    for (int s = 0; s < CL; s++) {
        size_t off = (size_t)s * EE;
        Aloc += lf[off];
        float A = A0 + Aloc;
        float t = lv[off] - A;
        if (t <= m) {
            r += expf(t - m);
        } else {
            r = r * expf(m - t) + 1.f;
            m = t;
        }
        ph[off] = __float2half_rn(expf(A + m) * r);
    }
}

// ---------------- launch ----------------
extern "C" void kernel_launch(void* const* d_in, const int* in_sizes, int n_in,
                              void* d_out, int out_size) {
    const float* x      = (const float*)d_in[0];
    const float* cdw_w  = (const float*)d_in[1];
    const float* cdw_b  = (const float*)d_in[2];
    const float* cpw_w  = (const float*)d_in[3];
    const float* cpw_b  = (const float*)d_in[4];
    const float* ln1_g  = (const float*)d_in[5];
    const float* ln1_b  = (const float*)d_in[6];
    const float* w_f    = (const float*)d_in[7];
    const float* w_i    = (const float*)d_in[8];
    const float* w_h    = (const float*)d_in[9];
    const float* w_down = (const float*)d_in[10];
    const float* ln2_g  = (const float*)d_in[11];
    const float* ln2_b  = (const float*)d_in[12];
    const float* mlp_w1 = (const float*)d_in[13];
    const float* mlp_b1 = (const float*)d_in[14];
    const float* mlp_w2 = (const float*)d_in[15];
    const float* mlp_b2 = (const float*)d_in[16];
    float* out = (float*)d_out;

    fp16 *dwa, *t1h, *x1a, *ha, *x2a, *ma;
    fp16 *pwh, *wgh, *wdh, *m1h, *m2h;
    float *gates;
    cudaGetSymbolAddress((void**)&dwa, g_dwa);
    cudaGetSymbolAddress((void**)&t1h, g_t1h);
    cudaGetSymbolAddress((void**)&x1a, g_x1a);
    cudaGetSymbolAddress((void**)&gates, g_gates);
    cudaGetSymbolAddress((void**)&ha,  g_ha);
    cudaGetSymbolAddress((void**)&x2a, g_x2a);
    cudaGetSymbolAddress((void**)&ma,  g_ma);
    cudaGetSymbolAddress((void**)&pwh, g_pwh);
    cudaGetSymbolAddress((void**)&wgh, g_wgh);
    cudaGetSymbolAddress((void**)&wdh, g_wdh);
    cudaGetSymbolAddress((void**)&m1h, g_m1h);
    cudaGetSymbolAddress((void**)&m2h, g_m2h);

    cudaFuncSetAttribute(hm_gemm<0,false,true>, cudaFuncAttributeMaxDynamicSharedMemorySize, GEMM_SMEM);
    cudaFuncSetAttribute(hm_gemm<4,true,false>, cudaFuncAttributeMaxDynamicSharedMemorySize, GEMM_SMEM);
    cudaFuncSetAttribute(hm_gemm<3,false,true>, cudaFuncAttributeMaxDynamicSharedMemorySize, GEMM_SMEM);
    cudaFuncSetAttribute(hm_gemm<0,true,false>, cudaFuncAttributeMaxDynamicSharedMemorySize, GEMM_SMEM);

    // 0,1) weight rounding (+ wi/wh interleave)
    splitA_kernel<<<(S_PW + 3*S_WG + 255)/256, 256>>>(cpw_w, w_f, w_i, w_h);
    splitB_kernel<<<(S_WD + 2*S_M + 255)/256, 256>>>(w_down, mlp_w1, mlp_w2);

    // 2) depthwise causal conv -> dwa (fp16)
    dwconv_kernel<<<(TT*DD)/256, 256>>>(x, cdw_w, cdw_b, dwa);

    // 3) pointwise conv + bias + residual(x) -> t1h (fp16)
    hm_gemm<0,false,true><<<dim3(DD/128, TT/128), 128, GEMM_SMEM>>>(
        dwa, pwh, cpw_b, x, nullptr, t1h, TT, DD, DD);

    // 4) LN1 -> x1a (fp16)
    ln_kernel<<<TT, 256>>>(t1h, ln1_g, ln1_b, x1a);

    // 5) fused gate GEMM -> 2 planes [lgf | lv]   [ncu captures this]
    hm_gemm<4,true,false><<<dim3(3*EE/128, TT/128), 128, GEMM_SMEM>>>(
        x1a, wgh, nullptr, nullptr, gates, nullptr, TT, 3*EE, DD);

    // 6-8) chunked scan -> h (fp16)
    scanA_kernel<<<(NC*NLANE + 127)/128, 128>>>(gates);
    scanB_kernel<<<(NLANE + 127)/128, 128>>>();
    scanC_kernel<<<(NC*NLANE + 127)/128, 128>>>(gates, ha);

    // 9) down GEMM + residual(x) -> t1h (fp16)
    hm_gemm<0,false,true><<<dim3(DD/128, TT/128), 128, GEMM_SMEM>>>(
        ha, wdh, nullptr, x, nullptr, t1h, TT, DD, EE);

    // 10) LN2 -> x2a (fp16)
    ln_kernel<<<TT, 256>>>(t1h, ln2_g, ln2_b, x2a);

    // 11) MLP up + bias + GELU -> ma (fp16)
    hm_gemm<3,false,true><<<dim3(HH/128, TT/128), 128, GEMM_SMEM>>>(
        x2a, m1h, mlp_b1, nullptr, nullptr, ma, TT, HH, DD);

    // 12) MLP down + bias -> out (fp32)
    hm_gemm<0,true,false><<<dim3(DD/128, TT/128), 128, GEMM_SMEM>>>(
        ma, m2h, mlp_b2, nullptr, out, nullptr, TT, DD, HH);
}

// round 14
// speedup vs baseline: 1.2066x; 1.2066x over previous
#include <cuda_runtime.h>
#include <cuda_fp16.h>
#include <cstdint>
#include <math.h>

#define BB 4
#define SS 2048
#define DD 1024
#define EE 1536
#define HH 4096
#define TT (BB*SS)   /* 8192 tokens */
#define NC 32        /* scan chunks */
#define CL (SS/NC)   /* 64 steps per chunk */
#define NLANE (BB*EE)

typedef __half fp16;

// ---------------- scratch (allocation-free: __device__ globals) ----------------
__device__ fp16  g_dwa[(size_t)TT*DD];
__device__ fp16  g_t1h[(size_t)TT*DD];         // residual stream pre-LN (fp16)
__device__ fp16  g_x1a[(size_t)TT*DD];
__device__ float g_gates[(size_t)2*TT*EE];     // [lgf | lv] planes
__device__ fp16  g_ha [(size_t)TT*EE];
__device__ fp16  g_x2a[(size_t)TT*DD];
__device__ fp16  g_ma [(size_t)TT*HH];
// chunked-scan state
__device__ float g_cA[NC*NLANE], g_cM[NC*NLANE], g_cR[NC*NLANE];
__device__ float g_pA[NC*NLANE], g_pM[NC*NLANE], g_pR[NC*NLANE];
// weights (fp16)
__device__ fp16 g_pwh[DD*DD];
__device__ fp16 g_wgh[3*EE*DD];   // rows [0,EE): w_f ; rows [EE,3EE): wi/wh 8-row interleave
__device__ fp16 g_wdh[DD*EE];
__device__ fp16 g_m1h[HH*DD];
__device__ fp16 g_m2h[DD*HH];

// ---------------- math helpers ----------------
__device__ __forceinline__ float logsig(float z) {
    return z >= 0.f ? -log1pf(expf(-z)) : z - log1pf(expf(z));
}
__device__ __forceinline__ float loggf(float x) {
    return x >= 0.f ? logf(x + 0.5f) : logsig(x);
}
__device__ __forceinline__ float gelu_exact(float x) {
    return 0.5f * x * (1.f + erff(x * 0.70710678118654752f));
}
template<int ACT>
__device__ __forceinline__ float apply_act(float v) {
    if (ACT == 1) return logsig(v);
    if (ACT == 3) return gelu_exact(v);
    return v;
}

__device__ __forceinline__ uint32_t smem_u32(const void* p) {
    uint32_t a;
    asm("{ .reg .u64 t; cvta.to.shared.u64 t, %1; cvt.u32.u64 %0, t; }" : "=r"(a) : "l"(p));
    return a;
}

#define LDMX4(d0,d1,d2,d3,addr) \
    asm volatile("ldmatrix.sync.aligned.m8n8.x4.shared.b16 {%0,%1,%2,%3}, [%4];" \
        : "=r"(d0), "=r"(d1), "=r"(d2), "=r"(d3) : "r"(addr))

__device__ __forceinline__ void mma16816(float* c, const uint32_t* a, const uint32_t* b) {
    asm volatile(
        "mma.sync.aligned.m16n8k16.row.col.f32.f16.f16.f32 "
        "{%0,%1,%2,%3}, {%4,%5,%6,%7}, {%8,%9}, {%0,%1,%2,%3};"
        : "+f"(c[0]), "+f"(c[1]), "+f"(c[2]), "+f"(c[3])
        : "r"(a[0]), "r"(a[1]), "r"(a[2]), "r"(a[3]), "r"(b[0]), "r"(b[1]));
}

// ---------------- HMMA GEMM (round-11 proven config) ----------------
// 128x128 tile, 256 thr (2x4 warps, 64x32 warp tile), BK=64, 2-stage, 2 CTA/SM.
static const int TILE_B  = 16384;
static const int STAGE_B = 2 * TILE_B;         // A, Bh
static const int GEMM_SMEM = 2 * STAGE_B + 1024;

// ACT==4: fused gate mode. bn<EE -> lgf plane (logsig). bn>=EE -> paired wi/wh
// fragments in the same thread; epilogue emits lv = logsig(zi)+loggf(zh).
template<int ACT, bool OUTF, bool OUTB>
__global__ __launch_bounds__(256, 2)
void hm_gemm(const fp16* __restrict__ A, const fp16* __restrict__ Bh,
             const float* __restrict__ bias, const float* __restrict__ res,
             float* __restrict__ Cf, fp16* __restrict__ Ch,
             int M, int N, int K)
{
    extern __shared__ char smem[];
    uint32_t sb = (smem_u32(smem) + 1023) & ~1023u;
    int tid = threadIdx.x;
    int lane = tid & 31, wid = tid >> 5;
    int wm = wid & 1, wn = wid >> 1;          // 2 x 4 warp grid
    int bm = blockIdx.y * 128, bn = blockIdx.x * 128;
    const int NK = K >> 6;

    float acc[4][4][4];
    #pragma unroll
    for (int i = 0; i < 4; i++)
        #pragma unroll
        for (int j = 0; j < 4; j++)
            #pragma unroll
            for (int q = 0; q < 4; q++) acc[i][j][q] = 0.f;

    auto load_chunk = [&](int c) {
        uint32_t tb = sb + (c & 1) * STAGE_B;
        int k0 = c << 6;
        #pragma unroll
        for (int i = 0; i < 8; i++) {
            int idx = tid + (i << 8);
            int t = i >> 2;
            int r = (idx >> 3) & 127;
            int ch = idx & 7;
            const fp16* base = (t == 0) ? A : Bh;
            int rowoff = (t == 0) ? bm : bn;
            const fp16* src = base + (size_t)(rowoff + r) * K + k0 + ch * 8;
            uint32_t dst = tb + t * TILE_B + r * 128 + ((ch ^ (r & 7)) * 16);
            asm volatile("cp.async.cg.shared.global [%0], [%1], 16;" :: "r"(dst), "l"(src));
        }
        asm volatile("cp.async.commit_group;");
    };

    load_chunk(0);

    for (int c = 0; c < NK; c++) {
        if (c + 1 < NK) {
            load_chunk(c + 1);
            asm volatile("cp.async.wait_group 1;");
        } else {
            asm volatile("cp.async.wait_group 0;");
        }
        __syncthreads();

        uint32_t tb  = sb + (c & 1) * STAGE_B;
        uint32_t tA  = tb;
        uint32_t tBh = tb + TILE_B;

        int khalf = lane >> 4;
        int rlo = lane & 15;

        #pragma unroll
        for (int sub = 0; sub < 4; sub++) {
            int c16 = sub * 2 + khalf;
            uint32_t bh[4][2];
            #pragma unroll
            for (int p = 0; p < 2; p++) {
                int r = wn * 32 + p * 16 + rlo;
                uint32_t addr = r * 128 + ((c16 ^ (r & 7)) * 16);
                uint32_t t0, t1, t2, t3;
                LDMX4(t0, t1, t2, t3, tBh + addr);
                bh[2*p][0] = t0; bh[2*p][1] = t2; bh[2*p+1][0] = t1; bh[2*p+1][1] = t3;
            }
            #pragma unroll
            for (int i = 0; i < 4; i++) {
                int r = wm * 64 + i * 16 + rlo;
                uint32_t addr = r * 128 + ((c16 ^ (r & 7)) * 16);
                uint32_t ah[4];
                LDMX4(ah[0], ah[1], ah[2], ah[3], tA + addr);
                #pragma unroll
                for (int j = 0; j < 4; j++) {
                    mma16816(acc[i][j], ah, bh[j]);
                }
            }
        }
        __syncthreads();
    }

    // ---- epilogue ----
    if (ACT == 4) {
        if (bn < EE) {
            // forget gate -> plane0 (lgf)
            #pragma unroll
            for (int i = 0; i < 4; i++) {
                #pragma unroll
                for (int j = 0; j < 4; j++) {
                    int r0 = bm + wm * 64 + i * 16 + (lane >> 2);
                    int c0 = bn + wn * 32 + j * 8 + (lane & 3) * 2;
                    #pragma unroll
                    for (int half = 0; half < 2; half++) {
                        int row = r0 + half * 8;
                        float v0 = logsig(acc[i][j][half * 2 + 0]);
                        float v1 = logsig(acc[i][j][half * 2 + 1]);
                        float2 w2; w2.x = v0; w2.y = v1;
                        *(float2*)(Cf + (size_t)row * EE + c0) = w2;
                    }
                }
            }
        } else {
            // combined wi/wh tiles -> plane1 (lv = logsig(zi) + loggf(zh))
            int qt = (bn - EE) >> 7;
            float* lvp = Cf + (size_t)TT * EE;
            #pragma unroll
            for (int i = 0; i < 4; i++) {
                #pragma unroll
                for (int j = 0; j < 4; j += 2) {
                    int r0 = bm + wm * 64 + i * 16 + (lane >> 2);
                    int grp = (wn * 4 + j) >> 1;
                    int e0 = qt * 64 + grp * 8 + (lane & 3) * 2;
                    #pragma unroll
                    for (int half = 0; half < 2; half++) {
                        int row = r0 + half * 8;
                        float v0 = logsig(acc[i][j][half*2+0]) + loggf(acc[i][j+1][half*2+0]);
                        float v1 = logsig(acc[i][j][half*2+1]) + loggf(acc[i][j+1][half*2+1]);
                        float2 w2; w2.x = v0; w2.y = v1;
                        *(float2*)(lvp + (size_t)row * EE + e0) = w2;
                    }
                }
            }
        }
        return;
    }

    #pragma unroll
    for (int i = 0; i < 4; i++) {
        #pragma unroll
        for (int j = 0; j < 4; j++) {
            int r0 = bm + wm * 64 + i * 16 + (lane >> 2);
            int c0 = bn + wn * 32 + j * 8 + (lane & 3) * 2;
            #pragma unroll
            for (int half = 0; half < 2; half++) {
                int row = r0 + half * 8;
                float v0 = acc[i][j][half * 2 + 0];
                float v1 = acc[i][j][half * 2 + 1];
                if (bias) { v0 += __ldg(bias + c0); v1 += __ldg(bias + c0 + 1); }
                v0 = apply_act<ACT>(v0);
                v1 = apply_act<ACT>(v1);
                size_t o = (size_t)row * N + c0;
                if (res) {
                    float2 r2 = *(const float2*)(res + o);
                    v0 += r2.x; v1 += r2.y;
                }
                if (OUTF) {
                    float2 w2; w2.x = v0; w2.y = v1;
                    *(float2*)(Cf + o) = w2;
                }
                if (OUTB) {
                    __half2 h2;
                    h2.x = __float2half_rn(v0);
                    h2.y = __float2half_rn(v1);
                    *(__half2*)(Ch + o) = h2;
                }
            }
        }
    }
}

// ---------------- weight rounding (fp32 -> fp16), single merged kernel ----------------
__device__ __forceinline__ void round4(const float* __restrict__ src,
                                       fp16* __restrict__ hi, int li) {
    float4 x = ((const float4*)src)[li];
    __half2 h0, h1;
    h0.x = __float2half_rn(x.x); h0.y = __float2half_rn(x.y);
    h1.x = __float2half_rn(x.z); h1.y = __float2half_rn(x.w);
    ((__half2*)hi)[2*li]   = h0;
    ((__half2*)hi)[2*li+1] = h1;
}
__device__ __forceinline__ void round4_sd(const float* __restrict__ src, int si,
                                          fp16* __restrict__ dst, int di) {
    float4 x = ((const float4*)src)[si];
    __half2 h0, h1;
    h0.x = __float2half_rn(x.x); h0.y = __float2half_rn(x.y);
    h1.x = __float2half_rn(x.z); h1.y = __float2half_rn(x.w);
    ((__half2*)dst)[2*di]   = h0;
    ((__half2*)dst)[2*di+1] = h1;
}

// segment sizes in float4 units
#define S_PW (DD*DD/4)
#define S_WG (EE*DD/4)
#define S_WD (DD*EE/4)
#define S_M  (HH*DD/4)
#define C4   (DD/4)     /* float4 per row */
#define S_ALL (S_PW + 3*S_WG + S_WD + 2*S_M)

__global__ void split_all_kernel(const float* __restrict__ pw, const float* __restrict__ wf,
                                 const float* __restrict__ wi, const float* __restrict__ wh,
                                 const float* __restrict__ wd, const float* __restrict__ m1,
                                 const float* __restrict__ m2) {
    int i = blockIdx.x * blockDim.x + threadIdx.x;
    if (i >= S_ALL) return;
    if (i < S_PW) { round4(pw, g_pwh, i); return; }
    int k = i - S_PW;
    if (k < S_WG) { round4(wf, g_wgh, k); return; }   // rows [0,EE): w_f
    if (k < 3*S_WG) {
        // interleaved wi/wh region: buffer rows [EE, 3EE)
        int k2 = k - S_WG;
        int r  = k2 / C4;
        int c4 = k2 % C4;
        int blk = r >> 4;
        int w   = r & 15;
        const float* src = (w < 8) ? wi : wh;
        int srow = blk * 8 + (w & 7);
        round4_sd(src, srow * C4 + c4, g_wgh, S_WG + k2);
        return;
    }
    int q = k - 3*S_WG;
    if (q < S_WD)            round4(wd, g_wdh, q);
    else if (q < S_WD + S_M) round4(m1, g_m1h, q - S_WD);
    else                     round4(m2, g_m2h, q - S_WD - S_M);
}

// ---------------- depthwise causal conv (K=4), emits fp16 ----------------
__global__ void dwconv_kernel(const float* __restrict__ x,
                              const float* __restrict__ w,
                              const float* __restrict__ b,
                              fp16* __restrict__ oa) {
    int idx = blockIdx.x * blockDim.x + threadIdx.x;
    int d = idx & (DD - 1);
    int t = idx >> 10;
    int s = t & (SS - 1);
    float acc = b[d];
    float w0 = w[d*4+0], w1 = w[d*4+1], w2 = w[d*4+2], w3 = w[d*4+3];
    if (s >= 3) acc += w0 * x[(size_t)(t-3)*DD + d];
    if (s >= 2) acc += w1 * x[(size_t)(t-2)*DD + d];
    if (s >= 1) acc += w2 * x[(size_t)(t-1)*DD + d];
    acc += w3 * x[(size_t)t*DD + d];
    oa[idx] = __float2half_rn(acc);
}

// ---------------- LayerNorm (D=1024), fp16 in, fp16 out ----------------
__global__ void ln_kernel(const fp16* __restrict__ in, const float* __restrict__ g,
                          const float* __restrict__ beta, fp16* __restrict__ oa) {
    int t = blockIdx.x;
    int i = threadIdx.x;   // 0..255, each 4 halves
    uint2 raw = ((const uint2*)(in + (size_t)t*DD))[i];
    __half2 p0 = *(__half2*)&raw.x;
    __half2 p1 = *(__half2*)&raw.y;
    float v0 = __half2float(p0.x), v1 = __half2float(p0.y);
    float v2 = __half2float(p1.x), v3 = __half2float(p1.y);
    float s  = v0 + v1 + v2 + v3;
    float s2 = v0*v0 + v1*v1 + v2*v2 + v3*v3;
    #pragma unroll
    for (int o = 16; o; o >>= 1) {
        s  += __shfl_xor_sync(0xffffffffu, s,  o);
        s2 += __shfl_xor_sync(0xffffffffu, s2, o);
    }
    __shared__ float ss[8], ss2[8];
    int w = i >> 5, l = i & 31;
    if (!l) { ss[w] = s; ss2[w] = s2; }
    __syncthreads();
    if (w == 0) {
        s  = (l < 8) ? ss[l]  : 0.f;
        s2 = (l < 8) ? ss2[l] : 0.f;
        #pragma unroll
        for (int o = 4; o; o >>= 1) {
            s  += __shfl_xor_sync(0xffffffffu, s,  o);
            s2 += __shfl_xor_sync(0xffffffffu, s2, o);
        }
        if (!l) { ss[0] = s; ss2[0] = s2; }
    }
    __syncthreads();
    float mu  = ss[0] * (1.f / DD);
    float var = ss2[0] * (1.f / DD) - mu * mu;
    float inv = rsqrtf(var + 1e-5f);
    float4 gg = ((const float4*)g)[i];
    float4 bb = ((const float4*)beta)[i];
    __half2 h0, h1;
    h0.x = __float2half_rn((v0 - mu) * inv * gg.x + bb.x);
    h0.y = __float2half_rn((v1 - mu) * inv * gg.y + bb.y);
    h1.x = __float2half_rn((v2 - mu) * inv * gg.z + bb.z);
    h1.y = __float2half_rn((v3 - mu) * inv * gg.w + bb.w);
    size_t base = (size_t)t * DD;
    ((__half2*)(oa + base))[2*i]   = h0;
    ((__half2*)(oa + base))[2*i+1] = h1;
}

// ---------------- chunked minLSTM scan: 3 phases (2-plane gates) ----------------
__global__ void scanA_kernel(const float* __restrict__ gates) {
    int id = blockIdx.x * blockDim.x + threadIdx.x;
    if (id >= NC * NLANE) return;
    int c = id / NLANE;
    int rem = id % NLANE;
    int b = rem / EE, e = rem % EE;
    const float* lf = gates + ((size_t)b * SS + c * CL) * EE + e;
    const float* lv = lf + (size_t)TT * EE;
    float Aloc = 0.f, M = -1e30f, R = 0.f;
    for (int s = 0; s < CL; s++) {
        size_t off = (size_t)s * EE;
        Aloc += lf[off];
        float t = lv[off] - Aloc;
        if (t <= M) {
            R += expf(t - M);
        } else {
            R = R * expf(M - t) + 1.f;
            M = t;
        }
    }
    g_cA[id] = Aloc; g_cM[id] = M; g_cR[id] = R;
}

__global__ void scanB_kernel() {
    int lane = blockIdx.x * blockDim.x + threadIdx.x;
    if (lane >= NLANE) return;
    float Aprev = 0.f;
    float Mg = -0.6931471805599453f;   // log 0.5
    float Rg = 1.f;
    #pragma unroll
    for (int c = 0; c < NC; c++) {
        int idx = c * NLANE + lane;
        g_pA[idx] = Aprev; g_pM[idx] = Mg; g_pR[idx] = Rg;
        float Mc = g_cM[idx] - Aprev;
        float Rc = g_cR[idx];
        if (Mc <= Mg) {
            Rg += Rc * expf(Mc - Mg);
        } else {
            Rg = Rg * expf(Mg - Mc) + Rc;
            Mg = Mc;
        }
        Aprev += g_cA[idx];
    }
}

__global__ void scanC_kernel(const float* __restrict__ gates, fp16* __restrict__ ha) {
    int id = blockIdx.x * blockDim.x + threadIdx.x;
    if (id >= NC * NLANE) return;
    int c = id / NLANE;
    int rem = id % NLANE;
    int b = rem / EE, e = rem % EE;
    const float* lf = gates + ((size_t)b * SS + c * CL) * EE + e;
    const float* lv = lf + (size_t)TT * EE;
    fp16* ph = ha + ((size_t)b * SS + c * CL) * EE + e;
    float A0 = g_pA[id];
    float m  = g_pM[id];
    float r  = g_pR[id];
    float Aloc = 0.f;
    for (int s = 0; s < CL; s++) {
        size_t off = (size_t)s * EE;
        Aloc += lf[off];
        float A = A0 + Aloc;
        float t = lv[off] - A;
        if (t <= m) {
            r += expf(t - m);
        } else {
            r = r * expf(m - t) + 1.f;
            m = t;
        }
        ph[off] = __float2half_rn(expf(A + m) * r);
    }
}

// ---------------- launch ----------------
extern "C" void kernel_launch(void* const* d_in, const int* in_sizes, int n_in,
                              void* d_out, int out_size) {
    const float* x      = (const float*)d_in[0];
    const float* cdw_w  = (const float*)d_in[1];
    const float* cdw_b  = (const float*)d_in[2];
    const float* cpw_w  = (const float*)d_in[3];
    const float* cpw_b  = (const float*)d_in[4];
    const float* ln1_g  = (const float*)d_in[5];
    const float* ln1_b  = (const float*)d_in[6];
    const float* w_f    = (const float*)d_in[7];
    const float* w_i    = (const float*)d_in[8];
    const float* w_h    = (const float*)d_in[9];
    const float* w_down = (const float*)d_in[10];
    const float* ln2_g  = (const float*)d_in[11];
    const float* ln2_b  = (const float*)d_in[12];
    const float* mlp_w1 = (const float*)d_in[13];
    const float* mlp_b1 = (const float*)d_in[14];
    const float* mlp_w2 = (const float*)d_in[15];
    const float* mlp_b2 = (const float*)d_in[16];
    float* out = (float*)d_out;

    fp16 *dwa, *t1h, *x1a, *ha, *x2a, *ma;
    fp16 *pwh, *wgh, *wdh, *m1h, *m2h;
    float *gates;
    cudaGetSymbolAddress((void**)&dwa, g_dwa);
    cudaGetSymbolAddress((void**)&t1h, g_t1h);
    cudaGetSymbolAddress((void**)&x1a, g_x1a);
    cudaGetSymbolAddress((void**)&gates, g_gates);
    cudaGetSymbolAddress((void**)&ha,  g_ha);
    cudaGetSymbolAddress((void**)&x2a, g_x2a);
    cudaGetSymbolAddress((void**)&ma,  g_ma);
    cudaGetSymbolAddress((void**)&pwh, g_pwh);
    cudaGetSymbolAddress((void**)&wgh, g_wgh);
    cudaGetSymbolAddress((void**)&wdh, g_wdh);
    cudaGetSymbolAddress((void**)&m1h, g_m1h);
    cudaGetSymbolAddress((void**)&m2h, g_m2h);

    cudaFuncSetAttribute(hm_gemm<0,false,true>, cudaFuncAttributeMaxDynamicSharedMemorySize, GEMM_SMEM);
    cudaFuncSetAttribute(hm_gemm<4,true,false>, cudaFuncAttributeMaxDynamicSharedMemorySize, GEMM_SMEM);
    cudaFuncSetAttribute(hm_gemm<3,false,true>, cudaFuncAttributeMaxDynamicSharedMemorySize, GEMM_SMEM);
    cudaFuncSetAttribute(hm_gemm<0,true,false>, cudaFuncAttributeMaxDynamicSharedMemorySize, GEMM_SMEM);

    // 0) weight rounding (+ wi/wh interleave), single kernel
    split_all_kernel<<<(S_ALL + 255)/256, 256>>>(cpw_w, w_f, w_i, w_h, w_down, mlp_w1, mlp_w2);

    // 1) depthwise causal conv -> dwa (fp16)
    dwconv_kernel<<<(TT*DD)/256, 256>>>(x, cdw_w, cdw_b, dwa);

    // 2) pointwise conv + bias + residual(x) -> t1h (fp16)
    hm_gemm<0,false,true><<<dim3(DD/128, TT/128), 256, GEMM_SMEM>>>(
        dwa, pwh, cpw_b, x, nullptr, t1h, TT, DD, DD);

    // 3) LN1 -> x1a (fp16)
    ln_kernel<<<TT, 256>>>(t1h, ln1_g, ln1_b, x1a);

    // 4) fused gate GEMM -> 2 planes [lgf | lv]
    hm_gemm<4,true,false><<<dim3(3*EE/128, TT/128), 256, GEMM_SMEM>>>(
        x1a, wgh, nullptr, nullptr, gates, nullptr, TT, 3*EE, DD);

    // 5-7) chunked scan -> h (fp16)
    scanA_kernel<<<(NC*NLANE + 127)/128, 128>>>(gates);
    scanB_kernel<<<(NLANE + 127)/128, 128>>>();
    scanC_kernel<<<(NC*NLANE + 127)/128, 128>>>(gates, ha);

    // 8) down GEMM + residual(x) -> t1h (fp16)
    hm_gemm<0,false,true><<<dim3(DD/128, TT/128), 256, GEMM_SMEM>>>(
        ha, wdh, nullptr, x, nullptr, t1h, TT, DD, EE);

    // 9) LN2 -> x2a (fp16)
    ln_kernel<<<TT, 256>>>(t1h, ln2_g, ln2_b, x2a);

    // 10) MLP up + bias + GELU -> ma (fp16)
    hm_gemm<3,false,true><<<dim3(HH/128, TT/128), 256, GEMM_SMEM>>>(
        x2a, m1h, mlp_b1, nullptr, nullptr, ma, TT, HH, DD);

    // 11) MLP down + bias -> out (fp32)
    hm_gemm<0,true,false><<<dim3(DD/128, TT/128), 256, GEMM_SMEM>>>(
        ma, m2h, mlp_b2, nullptr, out, nullptr, TT, DD, HH);
}

// round 15
// speedup vs baseline: 1.2211x; 1.0121x over previous
#include <cuda_runtime.h>
#include <cuda_fp16.h>
#include <cstdint>
#include <math.h>

#define BB 4
#define SS 2048
#define DD 1024
#define EE 1536
#define HH 4096
#define TT (BB*SS)   /* 8192 tokens */
#define NC 32        /* scan chunks */
#define CL (SS/NC)   /* 64 steps per chunk */
#define NLANE (BB*EE)

typedef __half fp16;

// ---------------- scratch (allocation-free: __device__ globals) ----------------
__device__ fp16  g_dwa[(size_t)TT*DD];
__device__ fp16  g_t1h[(size_t)TT*DD];         // residual stream pre-LN (fp16)
__device__ fp16  g_x1a[(size_t)TT*DD];
__device__ float g_lgf[(size_t)TT*EE];         // log f plane (fp32: cumsum-sensitive)
__device__ fp16  g_lv [(size_t)TT*EE];         // lv plane (fp16)
__device__ fp16  g_ha [(size_t)TT*EE];
__device__ fp16  g_x2a[(size_t)TT*DD];
__device__ fp16  g_ma [(size_t)TT*HH];
// chunked-scan state
__device__ float g_cA[NC*NLANE], g_cM[NC*NLANE], g_cR[NC*NLANE];
__device__ float g_pA[NC*NLANE], g_pM[NC*NLANE], g_pR[NC*NLANE];
// weights (fp16)
__device__ fp16 g_pwh[DD*DD];
__device__ fp16 g_wgh[3*EE*DD];   // rows [0,EE): w_f ; rows [EE,3EE): wi/wh 8-row interleave
__device__ fp16 g_wdh[DD*EE];
__device__ fp16 g_m1h[HH*DD];
__device__ fp16 g_m2h[DD*HH];

// ---------------- math helpers ----------------
__device__ __forceinline__ float logsig(float z) {
    return z >= 0.f ? -log1pf(expf(-z)) : z - log1pf(expf(z));
}
__device__ __forceinline__ float loggf(float x) {
    return x >= 0.f ? logf(x + 0.5f) : logsig(x);
}
__device__ __forceinline__ float gelu_exact(float x) {
    return 0.5f * x * (1.f + erff(x * 0.70710678118654752f));
}
template<int ACT>
__device__ __forceinline__ float apply_act(float v) {
    if (ACT == 1) return logsig(v);
    if (ACT == 3) return gelu_exact(v);
    return v;
}

__device__ __forceinline__ uint32_t smem_u32(const void* p) {
    uint32_t a;
    asm("{ .reg .u64 t; cvta.to.shared.u64 t, %1; cvt.u32.u64 %0, t; }" : "=r"(a) : "l"(p));
    return a;
}

#define LDMX4(d0,d1,d2,d3,addr) \
    asm volatile("ldmatrix.sync.aligned.m8n8.x4.shared.b16 {%0,%1,%2,%3}, [%4];" \
        : "=r"(d0), "=r"(d1), "=r"(d2), "=r"(d3) : "r"(addr))

__device__ __forceinline__ void mma16816(float* c, const uint32_t* a, const uint32_t* b) {
    asm volatile(
        "mma.sync.aligned.m16n8k16.row.col.f32.f16.f16.f32 "
        "{%0,%1,%2,%3}, {%4,%5,%6,%7}, {%8,%9}, {%0,%1,%2,%3};"
        : "+f"(c[0]), "+f"(c[1]), "+f"(c[2]), "+f"(c[3])
        : "r"(a[0]), "r"(a[1]), "r"(a[2]), "r"(a[3]), "r"(b[0]), "r"(b[1]));
}

// ---------------- HMMA GEMM (proven config) ----------------
// 128x128 tile, 256 thr (2x4 warps, 64x32 warp tile), BK=64, 2-stage, 2 CTA/SM.
static const int TILE_B  = 16384;
static const int STAGE_B = 2 * TILE_B;         // A, Bh
static const int GEMM_SMEM = 2 * STAGE_B + 1024;

// ACT==4: fused gate mode. bn<EE -> lgf plane fp32 (logsig) via Cf.
// bn>=EE -> paired wi/wh fragments; emits lv = logsig(zi)+loggf(zh) fp16 via Ch.
template<int ACT, bool OUTF, bool OUTB>
__global__ __launch_bounds__(256, 2)
void hm_gemm(const fp16* __restrict__ A, const fp16* __restrict__ Bh,
             const float* __restrict__ bias, const float* __restrict__ res,
             float* __restrict__ Cf, fp16* __restrict__ Ch,
             int M, int N, int K)
{
    extern __shared__ char smem[];
    uint32_t sb = (smem_u32(smem) + 1023) & ~1023u;
    int tid = threadIdx.x;
    int lane = tid & 31, wid = tid >> 5;
    int wm = wid & 1, wn = wid >> 1;          // 2 x 4 warp grid
    int bm = blockIdx.y * 128, bn = blockIdx.x * 128;
    const int NK = K >> 6;

    float acc[4][4][4];
    #pragma unroll
    for (int i = 0; i < 4; i++)
        #pragma unroll
        for (int j = 0; j < 4; j++)
            #pragma unroll
            for (int q = 0; q < 4; q++) acc[i][j][q] = 0.f;

    auto load_chunk = [&](int c) {
        uint32_t tb = sb + (c & 1) * STAGE_B;
        int k0 = c << 6;
        #pragma unroll
        for (int i = 0; i < 8; i++) {
            int idx = tid + (i << 8);
            int t = i >> 2;
            int r = (idx >> 3) & 127;
            int ch = idx & 7;
            const fp16* base = (t == 0) ? A : Bh;
            int rowoff = (t == 0) ? bm : bn;
            const fp16* src = base + (size_t)(rowoff + r) * K + k0 + ch * 8;
            uint32_t dst = tb + t * TILE_B + r * 128 + ((ch ^ (r & 7)) * 16);
            asm volatile("cp.async.cg.shared.global [%0], [%1], 16;" :: "r"(dst), "l"(src));
        }
        asm volatile("cp.async.commit_group;");
    };

    load_chunk(0);

    for (int c = 0; c < NK; c++) {
        if (c + 1 < NK) {
            load_chunk(c + 1);
            asm volatile("cp.async.wait_group 1;");
        } else {
            asm volatile("cp.async.wait_group 0;");
        }
        __syncthreads();

        uint32_t tb  = sb + (c & 1) * STAGE_B;
        uint32_t tA  = tb;
        uint32_t tBh = tb + TILE_B;

        int khalf = lane >> 4;
        int rlo = lane & 15;

        #pragma unroll
        for (int sub = 0; sub < 4; sub++) {
            int c16 = sub * 2 + khalf;
            uint32_t bh[4][2];
            #pragma unroll
            for (int p = 0; p < 2; p++) {
                int r = wn * 32 + p * 16 + rlo;
                uint32_t addr = r * 128 + ((c16 ^ (r & 7)) * 16);
                uint32_t t0, t1, t2, t3;
                LDMX4(t0, t1, t2, t3, tBh + addr);
                bh[2*p][0] = t0; bh[2*p][1] = t2; bh[2*p+1][0] = t1; bh[2*p+1][1] = t3;
            }
            #pragma unroll
            for (int i = 0; i < 4; i++) {
                int r = wm * 64 + i * 16 + rlo;
                uint32_t addr = r * 128 + ((c16 ^ (r & 7)) * 16);
                uint32_t ah[4];
                LDMX4(ah[0], ah[1], ah[2], ah[3], tA + addr);
                #pragma unroll
                for (int j = 0; j < 4; j++) {
                    mma16816(acc[i][j], ah, bh[j]);
                }
            }
        }
        __syncthreads();
    }

    // ---- epilogue ----
    if (ACT == 4) {
        if (bn < EE) {
            // forget gate -> lgf plane (fp32)
            #pragma unroll
            for (int i = 0; i < 4; i++) {
                #pragma unroll
                for (int j = 0; j < 4; j++) {
                    int r0 = bm + wm * 64 + i * 16 + (lane >> 2);
                    int c0 = bn + wn * 32 + j * 8 + (lane & 3) * 2;
                    #pragma unroll
                    for (int half = 0; half < 2; half++) {
                        int row = r0 + half * 8;
                        float v0 = logsig(acc[i][j][half * 2 + 0]);
                        float v1 = logsig(acc[i][j][half * 2 + 1]);
                        float2 w2; w2.x = v0; w2.y = v1;
                        *(float2*)(Cf + (size_t)row * EE + c0) = w2;
                    }
                }
            }
        } else {
            // combined wi/wh tiles -> lv plane (fp16): lv = logsig(zi) + loggf(zh)
            int qt = (bn - EE) >> 7;
            #pragma unroll
            for (int i = 0; i < 4; i++) {
                #pragma unroll
                for (int j = 0; j < 4; j += 2) {
                    int r0 = bm + wm * 64 + i * 16 + (lane >> 2);
                    int grp = (wn * 4 + j) >> 1;
                    int e0 = qt * 64 + grp * 8 + (lane & 3) * 2;
                    #pragma unroll
                    for (int half = 0; half < 2; half++) {
                        int row = r0 + half * 8;
                        float v0 = logsig(acc[i][j][half*2+0]) + loggf(acc[i][j+1][half*2+0]);
                        float v1 = logsig(acc[i][j][half*2+1]) + loggf(acc[i][j+1][half*2+1]);
                        __half2 h2;
                        h2.x = __float2half_rn(v0);
                        h2.y = __float2half_rn(v1);
                        *(__half2*)(Ch + (size_t)row * EE + e0) = h2;
                    }
                }
            }
        }
        return;
    }

    #pragma unroll
    for (int i = 0; i < 4; i++) {
        #pragma unroll
        for (int j = 0; j < 4; j++) {
            int r0 = bm + wm * 64 + i * 16 + (lane >> 2);
            int c0 = bn + wn * 32 + j * 8 + (lane & 3) * 2;
            #pragma unroll
            for (int half = 0; half < 2; half++) {
                int row = r0 + half * 8;
                float v0 = acc[i][j][half * 2 + 0];
                float v1 = acc[i][j][half * 2 + 1];
                if (bias) { v0 += __ldg(bias + c0); v1 += __ldg(bias + c0 + 1); }
                v0 = apply_act<ACT>(v0);
                v1 = apply_act<ACT>(v1);
                size_t o = (size_t)row * N + c0;
                if (res) {
                    float2 r2 = *(const float2*)(res + o);
                    v0 += r2.x; v1 += r2.y;
                }
                if (OUTF) {
                    float2 w2; w2.x = v0; w2.y = v1;
                    *(float2*)(Cf + o) = w2;
                }
                if (OUTB) {
                    __half2 h2;
                    h2.x = __float2half_rn(v0);
                    h2.y = __float2half_rn(v1);
                    *(__half2*)(Ch + o) = h2;
                }
            }
        }
    }
}

// ---------------- merged prep: weight rounding + interleave + dwconv ----------------
__device__ __forceinline__ void round4(const float* __restrict__ src,
                                       fp16* __restrict__ hi, int li) {
    float4 x = ((const float4*)src)[li];
    __half2 h0, h1;
    h0.x = __float2half_rn(x.x); h0.y = __float2half_rn(x.y);
    h1.x = __float2half_rn(x.z); h1.y = __float2half_rn(x.w);
    ((__half2*)hi)[2*li]   = h0;
    ((__half2*)hi)[2*li+1] = h1;
}
__device__ __forceinline__ void round4_sd(const float* __restrict__ src, int si,
                                          fp16* __restrict__ dst, int di) {
    float4 x = ((const float4*)src)[si];
    __half2 h0, h1;
    h0.x = __float2half_rn(x.x); h0.y = __float2half_rn(x.y);
    h1.x = __float2half_rn(x.z); h1.y = __float2half_rn(x.w);
    ((__half2*)dst)[2*di]   = h0;
    ((__half2*)dst)[2*di+1] = h1;
}

// segment sizes in float4 units
#define S_PW (DD*DD/4)
#define S_WG (EE*DD/4)
#define S_WD (DD*EE/4)
#define S_M  (HH*DD/4)
#define C4   (DD/4)     /* float4 per row */
#define S_ALL (S_PW + 3*S_WG + S_WD + 2*S_M)
#define SPLIT_BLOCKS ((S_ALL + 255)/256)
#define DW_BLOCKS ((TT*DD)/256)

__global__ void prep_kernel(const float* __restrict__ pw, const float* __restrict__ wf,
                            const float* __restrict__ wi, const float* __restrict__ wh,
                            const float* __restrict__ wd, const float* __restrict__ m1,
                            const float* __restrict__ m2,
                            const float* __restrict__ x,  const float* __restrict__ cw,
                            const float* __restrict__ cb, fp16* __restrict__ dwa) {
    int blk = blockIdx.x;
    if (blk >= SPLIT_BLOCKS) {
        // depthwise causal conv (K=4)
        int idx = (blk - SPLIT_BLOCKS) * 256 + threadIdx.x;
        int d = idx & (DD - 1);
        int t = idx >> 10;
        int s = t & (SS - 1);
        float acc = cb[d];
        float w0 = cw[d*4+0], w1 = cw[d*4+1], w2 = cw[d*4+2], w3 = cw[d*4+3];
        if (s >= 3) acc += w0 * x[(size_t)(t-3)*DD + d];
        if (s >= 2) acc += w1 * x[(size_t)(t-2)*DD + d];
        if (s >= 1) acc += w2 * x[(size_t)(t-1)*DD + d];
        acc += w3 * x[(size_t)t*DD + d];
        dwa[idx] = __float2half_rn(acc);
        return;
    }
    int i = blk * 256 + threadIdx.x;
    if (i >= S_ALL) return;
    if (i < S_PW) { round4(pw, g_pwh, i); return; }
    int k = i - S_PW;
    if (k < S_WG) { round4(wf, g_wgh, k); return; }   // rows [0,EE): w_f
    if (k < 3*S_WG) {
        // interleaved wi/wh region: buffer rows [EE, 3EE)
        int k2 = k - S_WG;
        int r  = k2 / C4;
        int c4 = k2 % C4;
        int b8 = r >> 4;
        int w  = r & 15;
        const float* src = (w < 8) ? wi : wh;
        int srow = b8 * 8 + (w & 7);
        round4_sd(src, srow * C4 + c4, g_wgh, S_WG + k2);
        return;
    }
    int q = k - 3*S_WG;
    if (q < S_WD)            round4(wd, g_wdh, q);
    else if (q < S_WD + S_M) round4(m1, g_m1h, q - S_WD);
    else                     round4(m2, g_m2h, q - S_WD - S_M);
}

// ---------------- LayerNorm: one warp per token, shuffle-only ----------------
__global__ void ln_kernel(const fp16* __restrict__ in, const float* __restrict__ g,
                          const float* __restrict__ beta, fp16* __restrict__ oa) {
    int warp = threadIdx.x >> 5, lane = threadIdx.x & 31;
    int t = blockIdx.x * 8 + warp;
    const uint4* row = (const uint4*)(in + (size_t)t * DD);   // 128 uint4 per row
    float vals[32];
    float s = 0.f, s2 = 0.f;
    #pragma unroll
    for (int j = 0; j < 4; j++) {
        uint4 v = row[lane + j * 32];
        const __half2* h = (const __half2*)&v;
        #pragma unroll
        for (int q = 0; q < 4; q++) {
            float a = __half2float(h[q].x);
            float b = __half2float(h[q].y);
            vals[j*8 + 2*q]     = a;
            vals[j*8 + 2*q + 1] = b;
            s  += a + b;
            s2 += a*a + b*b;
        }
    }
    #pragma unroll
    for (int o = 16; o; o >>= 1) {
        s  += __shfl_xor_sync(0xffffffffu, s,  o);
        s2 += __shfl_xor_sync(0xffffffffu, s2, o);
    }
    float mu  = s * (1.f / DD);
    float inv = rsqrtf(s2 * (1.f / DD) - mu * mu + 1e-5f);
    uint4* orow = (uint4*)(oa + (size_t)t * DD);
    const float4* Gp = (const float4*)g;
    const float4* Bp = (const float4*)beta;
    #pragma unroll
    for (int j = 0; j < 4; j++) {
        int u = lane + j * 32;                 // uint4 index (8 halves)
        float4 g0 = Gp[u*2],     g1 = Gp[u*2 + 1];
        float4 b0 = Bp[u*2],     b1 = Bp[u*2 + 1];
        uint4 o4;
        __half2* ho = (__half2*)&o4;
        ho[0].x = __float2half_rn((vals[j*8+0] - mu) * inv * g0.x + b0.x);
        ho[0].y = __float2half_rn((vals[j*8+1] - mu) * inv * g0.y + b0.y);
        ho[1].x = __float2half_rn((vals[j*8+2] - mu) * inv * g0.z + b0.z);
        ho[1].y = __float2half_rn((vals[j*8+3] - mu) * inv * g0.w + b0.w);
        ho[2].x = __float2half_rn((vals[j*8+4] - mu) * inv * g1.x + b1.x);
        ho[2].y = __float2half_rn((vals[j*8+5] - mu) * inv * g1.y + b1.y);
        ho[3].x = __float2half_rn((vals[j*8+6] - mu) * inv * g1.z + b1.z);
        ho[3].y = __float2half_rn((vals[j*8+7] - mu) * inv * g1.w + b1.w);
        orow[u] = o4;
    }
}

// ---------------- chunked minLSTM scan: 3 phases ----------------
__global__ void scanA_kernel(const float* __restrict__ lgf, const fp16* __restrict__ lv) {
    int id = blockIdx.x * blockDim.x + threadIdx.x;
    if (id >= NC * NLANE) return;
    int c = id / NLANE;
    int rem = id % NLANE;
    int b = rem / EE, e = rem % EE;
    const float* lf = lgf + ((size_t)b * SS + c * CL) * EE + e;
    const fp16* lvp = lv + ((size_t)b * SS + c * CL) * EE + e;
    float Aloc = 0.f, M = -1e30f, R = 0.f;
    for (int s = 0; s < CL; s++) {
        size_t off = (size_t)s * EE;
        Aloc += lf[off];
        float t = __half2float(lvp[off]) - Aloc;
        if (t <= M) {
            R += expf(t - M);
        } else {
            R = R * expf(M - t) + 1.f;
            M = t;
        }
    }
    g_cA[id] = Aloc; g_cM[id] = M; g_cR[id] = R;
}

__global__ void scanB_kernel() {
    int lane = blockIdx.x * blockDim.x + threadIdx.x;
    if (lane >= NLANE) return;
    float Aprev = 0.f;
    float Mg = -0.6931471805599453f;   // log 0.5
    float Rg = 1.f;
    #pragma unroll
    for (int c = 0; c < NC; c++) {
        int idx = c * NLANE + lane;
        g_pA[idx] = Aprev; g_pM[idx] = Mg; g_pR[idx] = Rg;
        float Mc = g_cM[idx] - Aprev;
        float Rc = g_cR[idx];
        if (Mc <= Mg) {
            Rg += Rc * expf(Mc - Mg);
        } else {
            Rg = Rg * expf(Mg - Mc) + Rc;
            Mg = Mc;
        }
        Aprev += g_cA[idx];
    }
}

__global__ void scanC_kernel(const float* __restrict__ lgf, const fp16* __restrict__ lv,
                             fp16* __restrict__ ha) {
    int id = blockIdx.x * blockDim.x + threadIdx.x;
    if (id >= NC * NLANE) return;
    int c = id / NLANE;
    int rem = id % NLANE;
    int b = rem / EE, e = rem % EE;
    const float* lf = lgf + ((size_t)b * SS + c * CL) * EE + e;
    const fp16* lvp = lv + ((size_t)b * SS + c * CL) * EE + e;
    fp16* ph = ha + ((size_t)b * SS + c * CL) * EE + e;
    float A0 = g_pA[id];
    float m  = g_pM[id];
    float r  = g_pR[id];
    float Aloc = 0.f;
    for (int s = 0; s < CL; s++) {
        size_t off = (size_t)s * EE;
        Aloc += lf[off];
        float A = A0 + Aloc;
        float t = __half2float(lvp[off]) - A;
        if (t <= m) {
            r += expf(t - m);
        } else {
            r = r * expf(m - t) + 1.f;
            m = t;
        }
        ph[off] = __float2half_rn(expf(A + m) * r);
    }
}

// ---------------- launch ----------------
extern "C" void kernel_launch(void* const* d_in, const int* in_sizes, int n_in,
                              void* d_out, int out_size) {
    const float* x      = (const float*)d_in[0];
    const float* cdw_w  = (const float*)d_in[1];
    const float* cdw_b  = (const float*)d_in[2];
    const float* cpw_w  = (const float*)d_in[3];
    const float* cpw_b  = (const float*)d_in[4];
    const float* ln1_g  = (const float*)d_in[5];
    const float* ln1_b  = (const float*)d_in[6];
    const float* w_f    = (const float*)d_in[7];
    const float* w_i    = (const float*)d_in[8];
    const float* w_h    = (const float*)d_in[9];
    const float* w_down = (const float*)d_in[10];
    const float* ln2_g  = (const float*)d_in[11];
    const float* ln2_b  = (const float*)d_in[12];
    const float* mlp_w1 = (const float*)d_in[13];
    const float* mlp_b1 = (const float*)d_in[14];
    const float* mlp_w2 = (const float*)d_in[15];
    const float* mlp_b2 = (const float*)d_in[16];
    float* out = (float*)d_out;

    fp16 *dwa, *t1h, *x1a, *lv, *ha, *x2a, *ma;
    fp16 *pwh, *wgh, *wdh, *m1h, *m2h;
    float *lgf;
    cudaGetSymbolAddress((void**)&dwa, g_dwa);
    cudaGetSymbolAddress((void**)&t1h, g_t1h);
    cudaGetSymbolAddress((void**)&x1a, g_x1a);
    cudaGetSymbolAddress((void**)&lgf, g_lgf);
    cudaGetSymbolAddress((void**)&lv,  g_lv);
    cudaGetSymbolAddress((void**)&ha,  g_ha);
    cudaGetSymbolAddress((void**)&x2a, g_x2a);
    cudaGetSymbolAddress((void**)&ma,  g_ma);
    cudaGetSymbolAddress((void**)&pwh, g_pwh);
    cudaGetSymbolAddress((void**)&wgh, g_wgh);
    cudaGetSymbolAddress((void**)&wdh, g_wdh);
    cudaGetSymbolAddress((void**)&m1h, g_m1h);
    cudaGetSymbolAddress((void**)&m2h, g_m2h);

    cudaFuncSetAttribute(hm_gemm<0,false,true>, cudaFuncAttributeMaxDynamicSharedMemorySize, GEMM_SMEM);
    cudaFuncSetAttribute(hm_gemm<4,true,false>, cudaFuncAttributeMaxDynamicSharedMemorySize, GEMM_SMEM);
    cudaFuncSetAttribute(hm_gemm<3,false,true>, cudaFuncAttributeMaxDynamicSharedMemorySize, GEMM_SMEM);
    cudaFuncSetAttribute(hm_gemm<0,true,false>, cudaFuncAttributeMaxDynamicSharedMemorySize, GEMM_SMEM);

    // 0) merged prep: weight rounding (+ wi/wh interleave) + dwconv
    prep_kernel<<<SPLIT_BLOCKS + DW_BLOCKS, 256>>>(
        cpw_w, w_f, w_i, w_h, w_down, mlp_w1, mlp_w2, x, cdw_w, cdw_b, dwa);

    // 1) pointwise conv + bias + residual(x) -> t1h (fp16)
    hm_gemm<0,false,true><<<dim3(DD/128, TT/128), 256, GEMM_SMEM>>>(
        dwa, pwh, cpw_b, x, nullptr, t1h, TT, DD, DD);

    // 2) LN1 -> x1a (fp16)
    ln_kernel<<<TT/8, 256>>>(t1h, ln1_g, ln1_b, x1a);

    // 3) fused gate GEMM -> lgf (fp32) + lv (fp16)
    hm_gemm<4,true,false><<<dim3(3*EE/128, TT/128), 256, GEMM_SMEM>>>(
        x1a, wgh, nullptr, nullptr, lgf, lv, TT, 3*EE, DD);

    // 4-6) chunked scan -> h (fp16)
    scanA_kernel<<<(NC*NLANE + 127)/128, 128>>>(lgf, lv);
    scanB_kernel<<<(NLANE + 127)/128, 128>>>();
    scanC_kernel<<<(NC*NLANE + 127)/128, 128>>>(lgf, lv, ha);

    // 7) down GEMM + residual(x) -> t1h (fp16)
    hm_gemm<0,false,true><<<dim3(DD/128, TT/128), 256, GEMM_SMEM>>>(
        ha, wdh, nullptr, x, nullptr, t1h, TT, DD, EE);

    // 8) LN2 -> x2a (fp16)
    ln_kernel<<<TT/8, 256>>>(t1h, ln2_g, ln2_b, x2a);

    // 9) MLP up + bias + GELU -> ma (fp16)
    hm_gemm<3,false,true><<<dim3(HH/128, TT/128), 256, GEMM_SMEM>>>(
        x2a, m1h, mlp_b1, nullptr, nullptr, ma, TT, HH, DD);

    // 10) MLP down + bias -> out (fp32)
    hm_gemm<0,true,false><<<dim3(DD/128, TT/128), 256, GEMM_SMEM>>>(
        ma, m2h, mlp_b2, nullptr, out, nullptr, TT, DD, HH);
}

// round 16
// speedup vs baseline: 1.2242x; 1.0025x over previous
#include <cuda_runtime.h>
#include <cuda_fp16.h>
#include <cstdint>
#include <math.h>

#define BB 4
#define SS 2048
#define DD 1024
#define EE 1536
#define HH 4096
#define TT (BB*SS)   /* 8192 tokens */
#define NC 64        /* scan chunks */
#define CL (SS/NC)   /* 32 steps per chunk */
#define NLANE (BB*EE)

typedef __half fp16;

// ---------------- scratch (allocation-free: __device__ globals) ----------------
__device__ fp16  g_dwa[(size_t)TT*DD];
__device__ fp16  g_t1h[(size_t)TT*DD];         // residual stream pre-LN (fp16)
__device__ fp16  g_x1a[(size_t)TT*DD];
__device__ float g_lgf[(size_t)TT*EE];         // log f plane (fp32: cumsum-sensitive)
__device__ fp16  g_lv [(size_t)TT*EE];         // lv plane (fp16)
__device__ fp16  g_ha [(size_t)TT*EE];
__device__ fp16  g_x2a[(size_t)TT*DD];
__device__ fp16  g_ma [(size_t)TT*HH];
// chunked-scan state
__device__ float g_cA[NC*NLANE], g_cM[NC*NLANE], g_cR[NC*NLANE];
__device__ float g_pA[NC*NLANE], g_pM[NC*NLANE], g_pR[NC*NLANE];
// weights (fp16)
__device__ fp16 g_pwh[DD*DD];
__device__ fp16 g_wgh[3*EE*DD];   // rows [0,EE): w_f ; rows [EE,3EE): wi/wh 8-row interleave
__device__ fp16 g_wdh[DD*EE];
__device__ fp16 g_m1h[HH*DD];
__device__ fp16 g_m2h[DD*HH];

// ---------------- math helpers ----------------
__device__ __forceinline__ float logsig(float z) {
    return z >= 0.f ? -log1pf(expf(-z)) : z - log1pf(expf(z));
}
__device__ __forceinline__ float loggf(float x) {
    return x >= 0.f ? logf(x + 0.5f) : logsig(x);
}
__device__ __forceinline__ float gelu_exact(float x) {
    return 0.5f * x * (1.f + erff(x * 0.70710678118654752f));
}
template<int ACT>
__device__ __forceinline__ float apply_act(float v) {
    if (ACT == 1) return logsig(v);
    if (ACT == 3) return gelu_exact(v);
    return v;
}

__device__ __forceinline__ uint32_t smem_u32(const void* p) {
    uint32_t a;
    asm("{ .reg .u64 t; cvta.to.shared.u64 t, %1; cvt.u32.u64 %0, t; }" : "=r"(a) : "l"(p));
    return a;
}

#define LDMX4(d0,d1,d2,d3,addr) \
    asm volatile("ldmatrix.sync.aligned.m8n8.x4.shared.b16 {%0,%1,%2,%3}, [%4];" \
        : "=r"(d0), "=r"(d1), "=r"(d2), "=r"(d3) : "r"(addr))

__device__ __forceinline__ void mma16816(float* c, const uint32_t* a, const uint32_t* b) {
    asm volatile(
        "mma.sync.aligned.m16n8k16.row.col.f32.f16.f16.f32 "
        "{%0,%1,%2,%3}, {%4,%5,%6,%7}, {%8,%9}, {%0,%1,%2,%3};"
        : "+f"(c[0]), "+f"(c[1]), "+f"(c[2]), "+f"(c[3])
        : "r"(a[0]), "r"(a[1]), "r"(a[2]), "r"(a[3]), "r"(b[0]), "r"(b[1]));
}

// ---------------- HMMA GEMM (proven config) ----------------
// 128x128 tile, 256 thr (2x4 warps, 64x32 warp tile), BK=64, 2-stage, 2 CTA/SM.
static const int TILE_B  = 16384;
static const int STAGE_B = 2 * TILE_B;         // A, Bh
static const int GEMM_SMEM = 2 * STAGE_B + 1024;

// ACT==4: fused gate mode. bn<EE -> lgf plane fp32 (logsig) via Cf.
// bn>=EE -> paired wi/wh fragments; emits lv = logsig(zi)+loggf(zh) fp16 via Ch.
template<int ACT, bool OUTF, bool OUTB>
__global__ __launch_bounds__(256, 2)
void hm_gemm(const fp16* __restrict__ A, const fp16* __restrict__ Bh,
             const float* __restrict__ bias, const float* __restrict__ res,
             float* __restrict__ Cf, fp16* __restrict__ Ch,
             int M, int N, int K)
{
    extern __shared__ char smem[];
    uint32_t sb = (smem_u32(smem) + 1023) & ~1023u;
    int tid = threadIdx.x;
    int lane = tid & 31, wid = tid >> 5;
    int wm = wid & 1, wn = wid >> 1;          // 2 x 4 warp grid
    int bm = blockIdx.y * 128, bn = blockIdx.x * 128;
    const int NK = K >> 6;

    float acc[4][4][4];
    #pragma unroll
    for (int i = 0; i < 4; i++)
        #pragma unroll
        for (int j = 0; j < 4; j++)
            #pragma unroll
            for (int q = 0; q < 4; q++) acc[i][j][q] = 0.f;

    auto load_chunk = [&](int c) {
        uint32_t tb = sb + (c & 1) * STAGE_B;
        int k0 = c << 6;
        #pragma unroll
        for (int i = 0; i < 8; i++) {
            int idx = tid + (i << 8);
            int t = i >> 2;
            int r = (idx >> 3) & 127;
            int ch = idx & 7;
            const fp16* base = (t == 0) ? A : Bh;
            int rowoff = (t == 0) ? bm : bn;
            const fp16* src = base + (size_t)(rowoff + r) * K + k0 + ch * 8;
            uint32_t dst = tb + t * TILE_B + r * 128 + ((ch ^ (r & 7)) * 16);
            asm volatile("cp.async.cg.shared.global [%0], [%1], 16;" :: "r"(dst), "l"(src));
        }
        asm volatile("cp.async.commit_group;");
    };

    load_chunk(0);

    for (int c = 0; c < NK; c++) {
        if (c + 1 < NK) {
            load_chunk(c + 1);
            asm volatile("cp.async.wait_group 1;");
        } else {
            asm volatile("cp.async.wait_group 0;");
        }
        __syncthreads();

        uint32_t tb  = sb + (c & 1) * STAGE_B;
        uint32_t tA  = tb;
        uint32_t tBh = tb + TILE_B;

        int khalf = lane >> 4;
        int rlo = lane & 15;

        #pragma unroll
        for (int sub = 0; sub < 4; sub++) {
            int c16 = sub * 2 + khalf;
            uint32_t bh[4][2];
            #pragma unroll
            for (int p = 0; p < 2; p++) {
                int r = wn * 32 + p * 16 + rlo;
                uint32_t addr = r * 128 + ((c16 ^ (r & 7)) * 16);
                uint32_t t0, t1, t2, t3;
                LDMX4(t0, t1, t2, t3, tBh + addr);
                bh[2*p][0] = t0; bh[2*p][1] = t2; bh[2*p+1][0] = t1; bh[2*p+1][1] = t3;
            }
            #pragma unroll
            for (int i = 0; i < 4; i++) {
                int r = wm * 64 + i * 16 + rlo;
                uint32_t addr = r * 128 + ((c16 ^ (r & 7)) * 16);
                uint32_t ah[4];
                LDMX4(ah[0], ah[1], ah[2], ah[3], tA + addr);
                #pragma unroll
                for (int j = 0; j < 4; j++) {
                    mma16816(acc[i][j], ah, bh[j]);
                }
            }
        }
        __syncthreads();
    }

    // ---- epilogue ----
    if (ACT == 4) {
        if (bn < EE) {
            // forget gate -> lgf plane (fp32)
            #pragma unroll
            for (int i = 0; i < 4; i++) {
                #pragma unroll
                for (int j = 0; j < 4; j++) {
                    int r0 = bm + wm * 64 + i * 16 + (lane >> 2);
                    int c0 = bn + wn * 32 + j * 8 + (lane & 3) * 2;
                    #pragma unroll
                    for (int half = 0; half < 2; half++) {
                        int row = r0 + half * 8;
                        float v0 = logsig(acc[i][j][half * 2 + 0]);
                        float v1 = logsig(acc[i][j][half * 2 + 1]);
                        float2 w2; w2.x = v0; w2.y = v1;
                        *(float2*)(Cf + (size_t)row * EE + c0) = w2;
                    }
                }
            }
        } else {
            // combined wi/wh tiles -> lv plane (fp16): lv = logsig(zi) + loggf(zh)
            int qt = (bn - EE) >> 7;
            #pragma unroll
            for (int i = 0; i < 4; i++) {
                #pragma unroll
                for (int j = 0; j < 4; j += 2) {
                    int r0 = bm + wm * 64 + i * 16 + (lane >> 2);
                    int grp = (wn * 4 + j) >> 1;
                    int e0 = qt * 64 + grp * 8 + (lane & 3) * 2;
                    #pragma unroll
                    for (int half = 0; half < 2; half++) {
                        int row = r0 + half * 8;
                        float v0 = logsig(acc[i][j][half*2+0]) + loggf(acc[i][j+1][half*2+0]);
                        float v1 = logsig(acc[i][j][half*2+1]) + loggf(acc[i][j+1][half*2+1]);
                        __half2 h2;
                        h2.x = __float2half_rn(v0);
                        h2.y = __float2half_rn(v1);
                        *(__half2*)(Ch + (size_t)row * EE + e0) = h2;
                    }
                }
            }
        }
        return;
    }

    #pragma unroll
    for (int i = 0; i < 4; i++) {
        #pragma unroll
        for (int j = 0; j < 4; j++) {
            int r0 = bm + wm * 64 + i * 16 + (lane >> 2);
            int c0 = bn + wn * 32 + j * 8 + (lane & 3) * 2;
            #pragma unroll
            for (int half = 0; half < 2; half++) {
                int row = r0 + half * 8;
                float v0 = acc[i][j][half * 2 + 0];
                float v1 = acc[i][j][half * 2 + 1];
                if (bias) { v0 += __ldg(bias + c0); v1 += __ldg(bias + c0 + 1); }
                v0 = apply_act<ACT>(v0);
                v1 = apply_act<ACT>(v1);
                size_t o = (size_t)row * N + c0;
                if (res) {
                    float2 r2 = *(const float2*)(res + o);
                    v0 += r2.x; v1 += r2.y;
                }
                if (OUTF) {
                    float2 w2; w2.x = v0; w2.y = v1;
                    *(float2*)(Cf + o) = w2;
                }
                if (OUTB) {
                    __half2 h2;
                    h2.x = __float2half_rn(v0);
                    h2.y = __float2half_rn(v1);
                    *(__half2*)(Ch + o) = h2;
                }
            }
        }
    }
}

// ---------------- merged prep: weight rounding + interleave + dwconv ----------------
__device__ __forceinline__ void round4(const float* __restrict__ src,
                                       fp16* __restrict__ hi, int li) {
    float4 x = ((const float4*)src)[li];
    __half2 h0, h1;
    h0.x = __float2half_rn(x.x); h0.y = __float2half_rn(x.y);
    h1.x = __float2half_rn(x.z); h1.y = __float2half_rn(x.w);
    ((__half2*)hi)[2*li]   = h0;
    ((__half2*)hi)[2*li+1] = h1;
}
__device__ __forceinline__ void round4_sd(const float* __restrict__ src, int si,
                                          fp16* __restrict__ dst, int di) {
    float4 x = ((const float4*)src)[si];
    __half2 h0, h1;
    h0.x = __float2half_rn(x.x); h0.y = __float2half_rn(x.y);
    h1.x = __float2half_rn(x.z); h1.y = __float2half_rn(x.w);
    ((__half2*)dst)[2*di]   = h0;
    ((__half2*)dst)[2*di+1] = h1;
}

// segment sizes in float4 units
#define S_PW (DD*DD/4)
#define S_WG (EE*DD/4)
#define S_WD (DD*EE/4)
#define S_M  (HH*DD/4)
#define C4   (DD/4)     /* float4 per row */
#define S_ALL (S_PW + 3*S_WG + S_WD + 2*S_M)
#define SPLIT_BLOCKS ((S_ALL + 255)/256)
#define DW_BLOCKS ((TT*DD)/256)

__global__ void prep_kernel(const float* __restrict__ pw, const float* __restrict__ wf,
                            const float* __restrict__ wi, const float* __restrict__ wh,
                            const float* __restrict__ wd, const float* __restrict__ m1,
                            const float* __restrict__ m2,
                            const float* __restrict__ x,  const float* __restrict__ cw,
                            const float* __restrict__ cb, fp16* __restrict__ dwa) {
    int blk = blockIdx.x;
    if (blk >= SPLIT_BLOCKS) {
        // depthwise causal conv (K=4)
        int idx = (blk - SPLIT_BLOCKS) * 256 + threadIdx.x;
        int d = idx & (DD - 1);
        int t = idx >> 10;
        int s = t & (SS - 1);
        float acc = cb[d];
        float w0 = cw[d*4+0], w1 = cw[d*4+1], w2 = cw[d*4+2], w3 = cw[d*4+3];
        if (s >= 3) acc += w0 * x[(size_t)(t-3)*DD + d];
        if (s >= 2) acc += w1 * x[(size_t)(t-2)*DD + d];
        if (s >= 1) acc += w2 * x[(size_t)(t-1)*DD + d];
        acc += w3 * x[(size_t)t*DD + d];
        dwa[idx] = __float2half_rn(acc);
        return;
    }
    int i = blk * 256 + threadIdx.x;
    if (i >= S_ALL) return;
    if (i < S_PW) { round4(pw, g_pwh, i); return; }
    int k = i - S_PW;
    if (k < S_WG) { round4(wf, g_wgh, k); return; }   // rows [0,EE): w_f
    if (k < 3*S_WG) {
        // interleaved wi/wh region: buffer rows [EE, 3EE)
        int k2 = k - S_WG;
        int r  = k2 / C4;
        int c4 = k2 % C4;
        int b8 = r >> 4;
        int w  = r & 15;
        const float* src = (w < 8) ? wi : wh;
        int srow = b8 * 8 + (w & 7);
        round4_sd(src, srow * C4 + c4, g_wgh, S_WG + k2);
        return;
    }
    int q = k - 3*S_WG;
    if (q < S_WD)            round4(wd, g_wdh, q);
    else if (q < S_WD + S_M) round4(m1, g_m1h, q - S_WD);
    else                     round4(m2, g_m2h, q - S_WD - S_M);
}

// ---------------- LayerNorm: one warp per token, shuffle-only ----------------
__global__ void ln_kernel(const fp16* __restrict__ in, const float* __restrict__ g,
                          const float* __restrict__ beta, fp16* __restrict__ oa) {
    int warp = threadIdx.x >> 5, lane = threadIdx.x & 31;
    int t = blockIdx.x * 8 + warp;
    const uint4* row = (const uint4*)(in + (size_t)t * DD);   // 128 uint4 per row
    float vals[32];
    float s = 0.f, s2 = 0.f;
    #pragma unroll
    for (int j = 0; j < 4; j++) {
        uint4 v = row[lane + j * 32];
        const __half2* h = (const __half2*)&v;
        #pragma unroll
        for (int q = 0; q < 4; q++) {
            float a = __half2float(h[q].x);
            float b = __half2float(h[q].y);
            vals[j*8 + 2*q]     = a;
            vals[j*8 + 2*q + 1] = b;
            s  += a + b;
            s2 += a*a + b*b;
        }
    }
    #pragma unroll
    for (int o = 16; o; o >>= 1) {
        s  += __shfl_xor_sync(0xffffffffu, s,  o);
        s2 += __shfl_xor_sync(0xffffffffu, s2, o);
    }
    float mu  = s * (1.f / DD);
    float inv = rsqrtf(s2 * (1.f / DD) - mu * mu + 1e-5f);
    uint4* orow = (uint4*)(oa + (size_t)t * DD);
    const float4* Gp = (const float4*)g;
    const float4* Bp = (const float4*)beta;
    #pragma unroll
    for (int j = 0; j < 4; j++) {
        int u = lane + j * 32;                 // uint4 index (8 halves)
        float4 g0 = Gp[u*2],     g1 = Gp[u*2 + 1];
        float4 b0 = Bp[u*2],     b1 = Bp[u*2 + 1];
        uint4 o4;
        __half2* ho = (__half2*)&o4;
        ho[0].x = __float2half_rn((vals[j*8+0] - mu) * inv * g0.x + b0.x);
        ho[0].y = __float2half_rn((vals[j*8+1] - mu) * inv * g0.y + b0.y);
        ho[1].x = __float2half_rn((vals[j*8+2] - mu) * inv * g0.z + b0.z);
        ho[1].y = __float2half_rn((vals[j*8+3] - mu) * inv * g0.w + b0.w);
        ho[2].x = __float2half_rn((vals[j*8+4] - mu) * inv * g1.x + b1.x);
        ho[2].y = __float2half_rn((vals[j*8+5] - mu) * inv * g1.y + b1.y);
        ho[3].x = __float2half_rn((vals[j*8+6] - mu) * inv * g1.z + b1.z);
        ho[3].y = __float2half_rn((vals[j*8+7] - mu) * inv * g1.w + b1.w);
        orow[u] = o4;
    }
}

// ---------------- chunked minLSTM scan: 3 phases (fast exp) ----------------
__global__ void scanA_kernel(const float* __restrict__ lgf, const fp16* __restrict__ lv) {
    int id = blockIdx.x * blockDim.x + threadIdx.x;
    if (id >= NC * NLANE) return;
    int c = id / NLANE;
    int rem = id % NLANE;
    int b = rem / EE, e = rem % EE;
    const float* lf = lgf + ((size_t)b * SS + c * CL) * EE + e;
    const fp16* lvp = lv + ((size_t)b * SS + c * CL) * EE + e;
    float Aloc = 0.f, M = -1e30f, R = 0.f;
    for (int s = 0; s < CL; s++) {
        size_t off = (size_t)s * EE;
        Aloc += lf[off];
        float t = __half2float(lvp[off]) - Aloc;
        if (t <= M) {
            R += __expf(t - M);
        } else {
            R = R * __expf(M - t) + 1.f;
            M = t;
        }
    }
    g_cA[id] = Aloc; g_cM[id] = M; g_cR[id] = R;
}

__global__ void scanB_kernel() {
    int lane = blockIdx.x * blockDim.x + threadIdx.x;
    if (lane >= NLANE) return;
    float Aprev = 0.f;
    float Mg = -0.6931471805599453f;   // log 0.5
    float Rg = 1.f;
    #pragma unroll 4
    for (int c = 0; c < NC; c++) {
        int idx = c * NLANE + lane;
        g_pA[idx] = Aprev; g_pM[idx] = Mg; g_pR[idx] = Rg;
        float Mc = g_cM[idx] - Aprev;
        float Rc = g_cR[idx];
        if (Mc <= Mg) {
            Rg += Rc * __expf(Mc - Mg);
        } else {
            Rg = Rg * __expf(Mg - Mc) + Rc;
            Mg = Mc;
        }
        Aprev += g_cA[idx];
    }
}

__global__ void scanC_kernel(const float* __restrict__ lgf, const fp16* __restrict__ lv,
                             fp16* __restrict__ ha) {
    int id = blockIdx.x * blockDim.x + threadIdx.x;
    if (id >= NC * NLANE) return;
    int c = id / NLANE;
    int rem = id % NLANE;
    int b = rem / EE, e = rem % EE;
    const float* lf = lgf + ((size_t)b * SS + c * CL) * EE + e;
    const fp16* lvp = lv + ((size_t)b * SS + c * CL) * EE + e;
    fp16* ph = ha + ((size_t)b * SS + c * CL) * EE + e;
    float A0 = g_pA[id];
    float m  = g_pM[id];
    float r  = g_pR[id];
    float Aloc = 0.f;
    for (int s = 0; s < CL; s++) {
        size_t off = (size_t)s * EE;
        Aloc += lf[off];
        float A = A0 + Aloc;
        float t = __half2float(lvp[off]) - A;
        if (t <= m) {
            r += __expf(t - m);
        } else {
            r = r * __expf(m - t) + 1.f;
            m = t;
        }
        ph[off] = __float2half_rn(__expf(A + m) * r);
    }
}

// ---------------- launch ----------------
extern "C" void kernel_launch(void* const* d_in, const int* in_sizes, int n_in,
                              void* d_out, int out_size) {
    const float* x      = (const float*)d_in[0];
    const float* cdw_w  = (const float*)d_in[1];
    const float* cdw_b  = (const float*)d_in[2];
    const float* cpw_w  = (const float*)d_in[3];
    const float* cpw_b  = (const float*)d_in[4];
    const float* ln1_g  = (const float*)d_in[5];
    const float* ln1_b  = (const float*)d_in[6];
    const float* w_f    = (const float*)d_in[7];
    const float* w_i    = (const float*)d_in[8];
    const float* w_h    = (const float*)d_in[9];
    const float* w_down = (const float*)d_in[10];
    const float* ln2_g  = (const float*)d_in[11];
    const float* ln2_b  = (const float*)d_in[12];
    const float* mlp_w1 = (const float*)d_in[13];
    const float* mlp_b1 = (const float*)d_in[14];
    const float* mlp_w2 = (const float*)d_in[15];
    const float* mlp_b2 = (const float*)d_in[16];
    float* out = (float*)d_out;

    fp16 *dwa, *t1h, *x1a, *lv, *ha, *x2a, *ma;
    fp16 *pwh, *wgh, *wdh, *m1h, *m2h;
    float *lgf;
    cudaGetSymbolAddress((void**)&dwa, g_dwa);
    cudaGetSymbolAddress((void**)&t1h, g_t1h);
    cudaGetSymbolAddress((void**)&x1a, g_x1a);
    cudaGetSymbolAddress((void**)&lgf, g_lgf);
    cudaGetSymbolAddress((void**)&lv,  g_lv);
    cudaGetSymbolAddress((void**)&ha,  g_ha);
    cudaGetSymbolAddress((void**)&x2a, g_x2a);
    cudaGetSymbolAddress((void**)&ma,  g_ma);
    cudaGetSymbolAddress((void**)&pwh, g_pwh);
    cudaGetSymbolAddress((void**)&wgh, g_wgh);
    cudaGetSymbolAddress((void**)&wdh, g_wdh);
    cudaGetSymbolAddress((void**)&m1h, g_m1h);
    cudaGetSymbolAddress((void**)&m2h, g_m2h);

    cudaFuncSetAttribute(hm_gemm<0,false,true>, cudaFuncAttributeMaxDynamicSharedMemorySize, GEMM_SMEM);
    cudaFuncSetAttribute(hm_gemm<4,true,false>, cudaFuncAttributeMaxDynamicSharedMemorySize, GEMM_SMEM);
    cudaFuncSetAttribute(hm_gemm<3,false,true>, cudaFuncAttributeMaxDynamicSharedMemorySize, GEMM_SMEM);
    cudaFuncSetAttribute(hm_gemm<0,true,false>, cudaFuncAttributeMaxDynamicSharedMemorySize, GEMM_SMEM);

    // 0) merged prep: weight rounding (+ wi/wh interleave) + dwconv
    prep_kernel<<<SPLIT_BLOCKS + DW_BLOCKS, 256>>>(
        cpw_w, w_f, w_i, w_h, w_down, mlp_w1, mlp_w2, x, cdw_w, cdw_b, dwa);

    // 1) pointwise conv + bias + residual(x) -> t1h (fp16)
    hm_gemm<0,false,true><<<dim3(DD/128, TT/128), 256, GEMM_SMEM>>>(
        dwa, pwh, cpw_b, x, nullptr, t1h, TT, DD, DD);

    // 2) LN1 -> x1a (fp16)
    ln_kernel<<<TT/8, 256>>>(t1h, ln1_g, ln1_b, x1a);

    // 3) fused gate GEMM -> lgf (fp32) + lv (fp16)
    hm_gemm<4,true,false><<<dim3(3*EE/128, TT/128), 256, GEMM_SMEM>>>(
        x1a, wgh, nullptr, nullptr, lgf, lv, TT, 3*EE, DD);

    // 4-6) chunked scan -> h (fp16)
    scanA_kernel<<<(NC*NLANE + 127)/128, 128>>>(lgf, lv);
    scanB_kernel<<<(NLANE + 127)/128, 128>>>();
    scanC_kernel<<<(NC*NLANE + 127)/128, 128>>>(lgf, lv, ha);

    // 7) down GEMM + residual(x) -> t1h (fp16)
    hm_gemm<0,false,true><<<dim3(DD/128, TT/128), 256, GEMM_SMEM>>>(
        ha, wdh, nullptr, x, nullptr, t1h, TT, DD, EE);

    // 8) LN2 -> x2a (fp16)
    ln_kernel<<<TT/8, 256>>>(t1h, ln2_g, ln2_b, x2a);

    // 9) MLP up + bias + GELU -> ma (fp16)
    hm_gemm<3,false,true><<<dim3(HH/128, TT/128), 256, GEMM_SMEM>>>(
        x2a, m1h, mlp_b1, nullptr, nullptr, ma, TT, HH, DD);

    // 10) MLP down + bias -> out (fp32)
    hm_gemm<0,true,false><<<dim3(DD/128, TT/128), 256, GEMM_SMEM>>>(
        ma, m2h, mlp_b2, nullptr, out, nullptr, TT, DD, HH);
}

// round 17
// speedup vs baseline: 1.2285x; 1.0035x over previous
#include <cuda_runtime.h>
#include <cuda_fp16.h>
#include <cstdint>
#include <math.h>

#define BB 4
#define SS 2048
#define DD 1024
#define EE 1536
#define HH 4096
#define TT (BB*SS)   /* 8192 tokens */
#define NC 64        /* scan chunks */
#define CL (SS/NC)   /* 32 steps per chunk */
#define NLANE (BB*EE)

typedef __half fp16;

// ---------------- scratch (allocation-free: __device__ globals) ----------------
__device__ fp16  g_dwa[(size_t)TT*DD];
__device__ fp16  g_t1h[(size_t)TT*DD];         // residual stream pre-LN (fp16)
__device__ fp16  g_x1a[(size_t)TT*DD];
__device__ fp16  g_gh [(size_t)2*TT*EE];       // [lgf | lv] planes, both fp16
__device__ fp16  g_ha [(size_t)TT*EE];
__device__ fp16  g_x2a[(size_t)TT*DD];
__device__ fp16  g_ma [(size_t)TT*HH];
// chunked-scan state
__device__ float g_cA[NC*NLANE], g_cM[NC*NLANE], g_cR[NC*NLANE];
__device__ float g_pA[NC*NLANE], g_pM[NC*NLANE], g_pR[NC*NLANE];
// weights (fp16)
__device__ fp16 g_pwh[DD*DD];
__device__ fp16 g_wgh[3*EE*DD];   // rows [0,EE): w_f ; rows [EE,3EE): wi/wh 8-row interleave
__device__ fp16 g_wdh[DD*EE];
__device__ fp16 g_m1h[HH*DD];
__device__ fp16 g_m2h[DD*HH];

// ---------------- math helpers ----------------
__device__ __forceinline__ float logsig(float z) {
    return z >= 0.f ? -log1pf(expf(-z)) : z - log1pf(expf(z));
}
__device__ __forceinline__ float loggf(float x) {
    return x >= 0.f ? logf(x + 0.5f) : logsig(x);
}
__device__ __forceinline__ float gelu_exact(float x) {
    return 0.5f * x * (1.f + erff(x * 0.70710678118654752f));
}
template<int ACT>
__device__ __forceinline__ float apply_act(float v) {
    if (ACT == 1) return logsig(v);
    if (ACT == 3) return gelu_exact(v);
    return v;
}

__device__ __forceinline__ uint32_t smem_u32(const void* p) {
    uint32_t a;
    asm("{ .reg .u64 t; cvta.to.shared.u64 t, %1; cvt.u32.u64 %0, t; }" : "=r"(a) : "l"(p));
    return a;
}

#define LDMX4(d0,d1,d2,d3,addr) \
    asm volatile("ldmatrix.sync.aligned.m8n8.x4.shared.b16 {%0,%1,%2,%3}, [%4];" \
        : "=r"(d0), "=r"(d1), "=r"(d2), "=r"(d3) : "r"(addr))

__device__ __forceinline__ void mma16816(float* c, const uint32_t* a, const uint32_t* b) {
    asm volatile(
        "mma.sync.aligned.m16n8k16.row.col.f32.f16.f16.f32 "
        "{%0,%1,%2,%3}, {%4,%5,%6,%7}, {%8,%9}, {%0,%1,%2,%3};"
        : "+f"(c[0]), "+f"(c[1]), "+f"(c[2]), "+f"(c[3])
        : "r"(a[0]), "r"(a[1]), "r"(a[2]), "r"(a[3]), "r"(b[0]), "r"(b[1]));
}

// ---------------- HMMA GEMM (proven config) ----------------
// 128x128 tile, 256 thr (2x4 warps, 64x32 warp tile), BK=64, 2-stage, 2 CTA/SM.
static const int TILE_B  = 16384;
static const int STAGE_B = 2 * TILE_B;         // A, Bh
static const int GEMM_SMEM = 2 * STAGE_B + 1024;

// ACT==4: fused gate mode, all-fp16 gate planes via Ch:
//   bn<EE  -> lgf = logsig(zf)            at Ch + row*EE + c
//   bn>=EE -> lv  = logsig(zi)+loggf(zh)  at Ch + TT*EE + row*EE + e
template<int ACT, bool OUTF, bool OUTB>
__global__ __launch_bounds__(256, 2)
void hm_gemm(const fp16* __restrict__ A, const fp16* __restrict__ Bh,
             const float* __restrict__ bias, const float* __restrict__ res,
             float* __restrict__ Cf, fp16* __restrict__ Ch,
             int M, int N, int K)
{
    extern __shared__ char smem[];
    uint32_t sb = (smem_u32(smem) + 1023) & ~1023u;
    int tid = threadIdx.x;
    int lane = tid & 31, wid = tid >> 5;
    int wm = wid & 1, wn = wid >> 1;          // 2 x 4 warp grid
    int bm = blockIdx.y * 128, bn = blockIdx.x * 128;
    const int NK = K >> 6;

    float acc[4][4][4];
    #pragma unroll
    for (int i = 0; i < 4; i++)
        #pragma unroll
        for (int j = 0; j < 4; j++)
            #pragma unroll
            for (int q = 0; q < 4; q++) acc[i][j][q] = 0.f;

    auto load_chunk = [&](int c) {
        uint32_t tb = sb + (c & 1) * STAGE_B;
        int k0 = c << 6;
        #pragma unroll
        for (int i = 0; i < 8; i++) {
            int idx = tid + (i << 8);
            int t = i >> 2;
            int r = (idx >> 3) & 127;
            int ch = idx & 7;
            const fp16* base = (t == 0) ? A : Bh;
            int rowoff = (t == 0) ? bm : bn;
            const fp16* src = base + (size_t)(rowoff + r) * K + k0 + ch * 8;
            uint32_t dst = tb + t * TILE_B + r * 128 + ((ch ^ (r & 7)) * 16);
            asm volatile("cp.async.cg.shared.global [%0], [%1], 16;" :: "r"(dst), "l"(src));
        }
        asm volatile("cp.async.commit_group;");
    };

    load_chunk(0);

    for (int c = 0; c < NK; c++) {
        if (c + 1 < NK) {
            load_chunk(c + 1);
            asm volatile("cp.async.wait_group 1;");
        } else {
            asm volatile("cp.async.wait_group 0;");
        }
        __syncthreads();

        uint32_t tb  = sb + (c & 1) * STAGE_B;
        uint32_t tA  = tb;
        uint32_t tBh = tb + TILE_B;

        int khalf = lane >> 4;
        int rlo = lane & 15;

        #pragma unroll
        for (int sub = 0; sub < 4; sub++) {
            int c16 = sub * 2 + khalf;
            uint32_t bh[4][2];
            #pragma unroll
            for (int p = 0; p < 2; p++) {
                int r = wn * 32 + p * 16 + rlo;
                uint32_t addr = r * 128 + ((c16 ^ (r & 7)) * 16);
                uint32_t t0, t1, t2, t3;
                LDMX4(t0, t1, t2, t3, tBh + addr);
                bh[2*p][0] = t0; bh[2*p][1] = t2; bh[2*p+1][0] = t1; bh[2*p+1][1] = t3;
            }
            #pragma unroll
            for (int i = 0; i < 4; i++) {
                int r = wm * 64 + i * 16 + rlo;
                uint32_t addr = r * 128 + ((c16 ^ (r & 7)) * 16);
                uint32_t ah[4];
                LDMX4(ah[0], ah[1], ah[2], ah[3], tA + addr);
                #pragma unroll
                for (int j = 0; j < 4; j++) {
                    mma16816(acc[i][j], ah, bh[j]);
                }
            }
        }
        __syncthreads();
    }

    // ---- epilogue ----
    if (ACT == 4) {
        if (bn < EE) {
            // forget gate -> lgf plane (fp16)
            #pragma unroll
            for (int i = 0; i < 4; i++) {
                #pragma unroll
                for (int j = 0; j < 4; j++) {
                    int r0 = bm + wm * 64 + i * 16 + (lane >> 2);
                    int c0 = bn + wn * 32 + j * 8 + (lane & 3) * 2;
                    #pragma unroll
                    for (int half = 0; half < 2; half++) {
                        int row = r0 + half * 8;
                        __half2 h2;
                        h2.x = __float2half_rn(logsig(acc[i][j][half * 2 + 0]));
                        h2.y = __float2half_rn(logsig(acc[i][j][half * 2 + 1]));
                        *(__half2*)(Ch + (size_t)row * EE + c0) = h2;
                    }
                }
            }
        } else {
            // combined wi/wh tiles -> lv plane (fp16): lv = logsig(zi) + loggf(zh)
            int qt = (bn - EE) >> 7;
            fp16* lvp = Ch + (size_t)TT * EE;
            #pragma unroll
            for (int i = 0; i < 4; i++) {
                #pragma unroll
                for (int j = 0; j < 4; j += 2) {
                    int r0 = bm + wm * 64 + i * 16 + (lane >> 2);
                    int grp = (wn * 4 + j) >> 1;
                    int e0 = qt * 64 + grp * 8 + (lane & 3) * 2;
                    #pragma unroll
                    for (int half = 0; half < 2; half++) {
                        int row = r0 + half * 8;
                        float v0 = logsig(acc[i][j][half*2+0]) + loggf(acc[i][j+1][half*2+0]);
                        float v1 = logsig(acc[i][j][half*2+1]) + loggf(acc[i][j+1][half*2+1]);
                        __half2 h2;
                        h2.x = __float2half_rn(v0);
                        h2.y = __float2half_rn(v1);
                        *(__half2*)(lvp + (size_t)row * EE + e0) = h2;
                    }
                }
            }
        }
        return;
    }

    #pragma unroll
    for (int i = 0; i < 4; i++) {
        #pragma unroll
        for (int j = 0; j < 4; j++) {
            int r0 = bm + wm * 64 + i * 16 + (lane >> 2);
            int c0 = bn + wn * 32 + j * 8 + (lane & 3) * 2;
            #pragma unroll
            for (int half = 0; half < 2; half++) {
                int row = r0 + half * 8;
                float v0 = acc[i][j][half * 2 + 0];
                float v1 = acc[i][j][half * 2 + 1];
                if (bias) { v0 += __ldg(bias + c0); v1 += __ldg(bias + c0 + 1); }
                v0 = apply_act<ACT>(v0);
                v1 = apply_act<ACT>(v1);
                size_t o = (size_t)row * N + c0;
                if (res) {
                    float2 r2 = *(const float2*)(res + o);
                    v0 += r2.x; v1 += r2.y;
                }
                if (OUTF) {
                    float2 w2; w2.x = v0; w2.y = v1;
                    *(float2*)(Cf + o) = w2;
                }
                if (OUTB) {
                    __half2 h2;
                    h2.x = __float2half_rn(v0);
                    h2.y = __float2half_rn(v1);
                    *(__half2*)(Ch + o) = h2;
                }
            }
        }
    }
}

// ---------------- merged prep: weight rounding + interleave + dwconv ----------------
__device__ __forceinline__ void round4(const float* __restrict__ src,
                                       fp16* __restrict__ hi, int li) {
    float4 x = ((const float4*)src)[li];
    __half2 h0, h1;
    h0.x = __float2half_rn(x.x); h0.y = __float2half_rn(x.y);
    h1.x = __float2half_rn(x.z); h1.y = __float2half_rn(x.w);
    ((__half2*)hi)[2*li]   = h0;
    ((__half2*)hi)[2*li+1] = h1;
}
__device__ __forceinline__ void round4_sd(const float* __restrict__ src, int si,
                                          fp16* __restrict__ dst, int di) {
    float4 x = ((const float4*)src)[si];
    __half2 h0, h1;
    h0.x = __float2half_rn(x.x); h0.y = __float2half_rn(x.y);
    h1.x = __float2half_rn(x.z); h1.y = __float2half_rn(x.w);
    ((__half2*)dst)[2*di]   = h0;
    ((__half2*)dst)[2*di+1] = h1;
}

// segment sizes in float4 units
#define S_PW (DD*DD/4)
#define S_WG (EE*DD/4)
#define S_WD (DD*EE/4)
#define S_M  (HH*DD/4)
#define C4   (DD/4)     /* float4 per row */
#define S_ALL (S_PW + 3*S_WG + S_WD + 2*S_M)
#define SPLIT_BLOCKS ((S_ALL + 255)/256)
#define DW_BLOCKS ((TT*DD)/256)

__global__ void prep_kernel(const float* __restrict__ pw, const float* __restrict__ wf,
                            const float* __restrict__ wi, const float* __restrict__ wh,
                            const float* __restrict__ wd, const float* __restrict__ m1,
                            const float* __restrict__ m2,
                            const float* __restrict__ x,  const float* __restrict__ cw,
                            const float* __restrict__ cb, fp16* __restrict__ dwa) {
    int blk = blockIdx.x;
    if (blk >= SPLIT_BLOCKS) {
        // depthwise causal conv (K=4)
        int idx = (blk - SPLIT_BLOCKS) * 256 + threadIdx.x;
        int d = idx & (DD - 1);
        int t = idx >> 10;
        int s = t & (SS - 1);
        float acc = cb[d];
        float w0 = cw[d*4+0], w1 = cw[d*4+1], w2 = cw[d*4+2], w3 = cw[d*4+3];
        if (s >= 3) acc += w0 * x[(size_t)(t-3)*DD + d];
        if (s >= 2) acc += w1 * x[(size_t)(t-2)*DD + d];
        if (s >= 1) acc += w2 * x[(size_t)(t-1)*DD + d];
        acc += w3 * x[(size_t)t*DD + d];
        dwa[idx] = __float2half_rn(acc);
        return;
    }
    int i = blk * 256 + threadIdx.x;
    if (i >= S_ALL) return;
    if (i < S_PW) { round4(pw, g_pwh, i); return; }
    int k = i - S_PW;
    if (k < S_WG) { round4(wf, g_wgh, k); return; }   // rows [0,EE): w_f
    if (k < 3*S_WG) {
        // interleaved wi/wh region: buffer rows [EE, 3EE)
        int k2 = k - S_WG;
        int r  = k2 / C4;
        int c4 = k2 % C4;
        int b8 = r >> 4;
        int w  = r & 15;
        const float* src = (w < 8) ? wi : wh;
        int srow = b8 * 8 + (w & 7);
        round4_sd(src, srow * C4 + c4, g_wgh, S_WG + k2);
        return;
    }
    int q = k - 3*S_WG;
    if (q < S_WD)            round4(wd, g_wdh, q);
    else if (q < S_WD + S_M) round4(m1, g_m1h, q - S_WD);
    else                     round4(m2, g_m2h, q - S_WD - S_M);
}

// ---------------- LayerNorm: one warp per token, shuffle-only ----------------
__global__ void ln_kernel(const fp16* __restrict__ in, const float* __restrict__ g,
                          const float* __restrict__ beta, fp16* __restrict__ oa) {
    int warp = threadIdx.x >> 5, lane = threadIdx.x & 31;
    int t = blockIdx.x * 8 + warp;
    const uint4* row = (const uint4*)(in + (size_t)t * DD);   // 128 uint4 per row
    float vals[32];
    float s = 0.f, s2 = 0.f;
    #pragma unroll
    for (int j = 0; j < 4; j++) {
        uint4 v = row[lane + j * 32];
        const __half2* h = (const __half2*)&v;
        #pragma unroll
        for (int q = 0; q < 4; q++) {
            float a = __half2float(h[q].x);
            float b = __half2float(h[q].y);
            vals[j*8 + 2*q]     = a;
            vals[j*8 + 2*q + 1] = b;
            s  += a + b;
            s2 += a*a + b*b;
        }
    }
    #pragma unroll
    for (int o = 16; o; o >>= 1) {
        s  += __shfl_xor_sync(0xffffffffu, s,  o);
        s2 += __shfl_xor_sync(0xffffffffu, s2, o);
    }
    float mu  = s * (1.f / DD);
    float inv = rsqrtf(s2 * (1.f / DD) - mu * mu + 1e-5f);
    uint4* orow = (uint4*)(oa + (size_t)t * DD);
    const float4* Gp = (const float4*)g;
    const float4* Bp = (const float4*)beta;
    #pragma unroll
    for (int j = 0; j < 4; j++) {
        int u = lane + j * 32;                 // uint4 index (8 halves)
        float4 g0 = Gp[u*2],     g1 = Gp[u*2 + 1];
        float4 b0 = Bp[u*2],     b1 = Bp[u*2 + 1];
        uint4 o4;
        __half2* ho = (__half2*)&o4;
        ho[0].x = __float2half_rn((vals[j*8+0] - mu) * inv * g0.x + b0.x);
        ho[0].y = __float2half_rn((vals[j*8+1] - mu) * inv * g0.y + b0.y);
        ho[1].x = __float2half_rn((vals[j*8+2] - mu) * inv * g0.z + b0.z);
        ho[1].y = __float2half_rn((vals[j*8+3] - mu) * inv * g0.w + b0.w);
        ho[2].x = __float2half_rn((vals[j*8+4] - mu) * inv * g1.x + b1.x);
        ho[2].y = __float2half_rn((vals[j*8+5] - mu) * inv * g1.y + b1.y);
        ho[3].x = __float2half_rn((vals[j*8+6] - mu) * inv * g1.z + b1.z);
        ho[3].y = __float2half_rn((vals[j*8+7] - mu) * inv * g1.w + b1.w);
        orow[u] = o4;
    }
}

// ---------------- chunked minLSTM scan: 3 phases (fp16 gates, fast exp) ----------------
__global__ void scanA_kernel(const fp16* __restrict__ gh) {
    int id = blockIdx.x * blockDim.x + threadIdx.x;
    if (id >= NC * NLANE) return;
    int c = id / NLANE;
    int rem = id % NLANE;
    int b = rem / EE, e = rem % EE;
    const fp16* lf  = gh + ((size_t)b * SS + c * CL) * EE + e;
    const fp16* lvp = lf + (size_t)TT * EE;
    float Aloc = 0.f, M = -1e30f, R = 0.f;
    for (int s = 0; s < CL; s++) {
        size_t off = (size_t)s * EE;
        Aloc += __half2float(lf[off]);
        float t = __half2float(lvp[off]) - Aloc;
        if (t <= M) {
            R += __expf(t - M);
        } else {
            R = R * __expf(M - t) + 1.f;
            M = t;
        }
    }
    g_cA[id] = Aloc; g_cM[id] = M; g_cR[id] = R;
}

__global__ void scanB_kernel() {
    int lane = blockIdx.x * blockDim.x + threadIdx.x;
    if (lane >= NLANE) return;
    float Aprev = 0.f;
    float Mg = -0.6931471805599453f;   // log 0.5
    float Rg = 1.f;
    #pragma unroll 4
    for (int c = 0; c < NC; c++) {
        int idx = c * NLANE + lane;
        g_pA[idx] = Aprev; g_pM[idx] = Mg; g_pR[idx] = Rg;
        float Mc = g_cM[idx] - Aprev;
        float Rc = g_cR[idx];
        if (Mc <= Mg) {
            Rg += Rc * __expf(Mc - Mg);
        } else {
            Rg = Rg * __expf(Mg - Mc) + Rc;
            Mg = Mc;
        }
        Aprev += g_cA[idx];
    }
}

__global__ void scanC_kernel(const fp16* __restrict__ gh, fp16* __restrict__ ha) {
    int id = blockIdx.x * blockDim.x + threadIdx.x;
    if (id >= NC * NLANE) return;
    int c = id / NLANE;
    int rem = id % NLANE;
    int b = rem / EE, e = rem % EE;
    const fp16* lf  = gh + ((size_t)b * SS + c * CL) * EE + e;
    const fp16* lvp = lf + (size_t)TT * EE;
    fp16* ph = ha + ((size_t)b * SS + c * CL) * EE + e;
    float A0 = g_pA[id];
    float m  = g_pM[id];
    float r  = g_pR[id];
    float Aloc = 0.f;
    for (int s = 0; s < CL; s++) {
        size_t off = (size_t)s * EE;
        Aloc += __half2float(lf[off]);
        float A = A0 + Aloc;
        float t = __half2float(lvp[off]) - A;
        if (t <= m) {
            r += __expf(t - m);
        } else {
            r = r * __expf(m - t) + 1.f;
            m = t;
        }
        ph[off] = __float2half_rn(__expf(A + m) * r);
    }
}

// ---------------- launch ----------------
extern "C" void kernel_launch(void* const* d_in, const int* in_sizes, int n_in,
                              void* d_out, int out_size) {
    const float* x      = (const float*)d_in[0];
    const float* cdw_w  = (const float*)d_in[1];
    const float* cdw_b  = (const float*)d_in[2];
    const float* cpw_w  = (const float*)d_in[3];
    const float* cpw_b  = (const float*)d_in[4];
    const float* ln1_g  = (const float*)d_in[5];
    const float* ln1_b  = (const float*)d_in[6];
    const float* w_f    = (const float*)d_in[7];
    const float* w_i    = (const float*)d_in[8];
    const float* w_h    = (const float*)d_in[9];
    const float* w_down = (const float*)d_in[10];
    const float* ln2_g  = (const float*)d_in[11];
    const float* ln2_b  = (const float*)d_in[12];
    const float* mlp_w1 = (const float*)d_in[13];
    const float* mlp_b1 = (const float*)d_in[14];
    const float* mlp_w2 = (const float*)d_in[15];
    const float* mlp_b2 = (const float*)d_in[16];
    float* out = (float*)d_out;

    fp16 *dwa, *t1h, *x1a, *gh, *ha, *x2a, *ma;
    fp16 *pwh, *wgh, *wdh, *m1h, *m2h;
    cudaGetSymbolAddress((void**)&dwa, g_dwa);
    cudaGetSymbolAddress((void**)&t1h, g_t1h);
    cudaGetSymbolAddress((void**)&x1a, g_x1a);
    cudaGetSymbolAddress((void**)&gh,  g_gh);
    cudaGetSymbolAddress((void**)&ha,  g_ha);
    cudaGetSymbolAddress((void**)&x2a, g_x2a);
    cudaGetSymbolAddress((void**)&ma,  g_ma);
    cudaGetSymbolAddress((void**)&pwh, g_pwh);
    cudaGetSymbolAddress((void**)&wgh, g_wgh);
    cudaGetSymbolAddress((void**)&wdh, g_wdh);
    cudaGetSymbolAddress((void**)&m1h, g_m1h);
    cudaGetSymbolAddress((void**)&m2h, g_m2h);

    cudaFuncSetAttribute(hm_gemm<0,false,true>, cudaFuncAttributeMaxDynamicSharedMemorySize, GEMM_SMEM);
    cudaFuncSetAttribute(hm_gemm<4,false,true>, cudaFuncAttributeMaxDynamicSharedMemorySize, GEMM_SMEM);
    cudaFuncSetAttribute(hm_gemm<3,false,true>, cudaFuncAttributeMaxDynamicSharedMemorySize, GEMM_SMEM);
    cudaFuncSetAttribute(hm_gemm<0,true,false>, cudaFuncAttributeMaxDynamicSharedMemorySize, GEMM_SMEM);

    // 0) merged prep: weight rounding (+ wi/wh interleave) + dwconv
    prep_kernel<<<SPLIT_BLOCKS + DW_BLOCKS, 256>>>(
        cpw_w, w_f, w_i, w_h, w_down, mlp_w1, mlp_w2, x, cdw_w, cdw_b, dwa);

    // 1) pointwise conv + bias + residual(x) -> t1h (fp16)
    hm_gemm<0,false,true><<<dim3(DD/128, TT/128), 256, GEMM_SMEM>>>(
        dwa, pwh, cpw_b, x, nullptr, t1h, TT, DD, DD);

    // 2) LN1 -> x1a (fp16)
    ln_kernel<<<TT/8, 256>>>(t1h, ln1_g, ln1_b, x1a);

    // 3) fused gate GEMM -> fp16 planes [lgf | lv]
    hm_gemm<4,false,true><<<dim3(3*EE/128, TT/128), 256, GEMM_SMEM>>>(
        x1a, wgh, nullptr, nullptr, nullptr, gh, TT, 3*EE, DD);

    // 4-6) chunked scan -> h (fp16)
    scanA_kernel<<<(NC*NLANE + 127)/128, 128>>>(gh);
    scanB_kernel<<<(NLANE + 127)/128, 128>>>();
    scanC_kernel<<<(NC*NLANE + 127)/128, 128>>>(gh, ha);

    // 7) down GEMM + residual(x) -> t1h (fp16)
    hm_gemm<0,false,true><<<dim3(DD/128, TT/128), 256, GEMM_SMEM>>>(
        ha, wdh, nullptr, x, nullptr, t1h, TT, DD, EE);

    // 8) LN2 -> x2a (fp16)
    ln_kernel<<<TT/8, 256>>>(t1h, ln2_g, ln2_b, x2a);

    // 9) MLP up + bias + GELU -> ma (fp16)
    hm_gemm<3,false,true><<<dim3(HH/128, TT/128), 256, GEMM_SMEM>>>(
        x2a, m1h, mlp_b1, nullptr, nullptr, ma, TT, HH, DD);

    // 10) MLP down + bias -> out (fp32)
    hm_gemm<0,true,false><<<dim3(DD/128, TT/128), 256, GEMM_SMEM>>>(
        ma, m2h, mlp_b2, nullptr, out, nullptr, TT, DD, HH);
}